// round 10
// baseline (speedup 1.0000x reference)
#include <cuda_runtime.h>
#include <cuda_bf16.h>
#include <cuda_fp16.h>
#include <cstdint>
#include <math.h>

#define E_EDGES 500000
#define NOLD    100000
#define NNEW    100000
#define NENT    100000
#define NREL    500
#define D_EMB   100
#define H_DIM   128
#define G3H     384

// ---------------- scratch (device globals; no allocation allowed) ----------------
__device__ __align__(16) float    g_node_s[NOLD * H_DIM];      // node_emb @ Ws^T (fp32)
__device__ __align__(16) __half   g_node_hh[NOLD * G3H];       // node_emb @ W_hh^T (fp16)
__device__ __align__(16) __half   g_ent_proj[NENT * G3H];      // ent_table @ W_ih[:, :100]^T (fp16)
__device__ __align__(16) float    g_rel_wr[NREL * H_DIM];
__device__ __align__(16) float    g_rel_wqr[NREL * H_DIM];
__device__ __align__(16) float    g_rel_gru[NREL * G3H];
__device__ float                  g_logit[E_EDGES];
__device__ float                  g_ex[E_EDGES];
__device__ unsigned               g_segmax[NNEW];
__device__ float                  g_denom[NNEW];
__device__ __align__(16) float    g_agg[NNEW * H_DIM];
// bf16 split planes (logit path only)
__device__ __align__(16) __nv_bfloat16 g_A_hi[NOLD * 128];
__device__ __align__(16) __nv_bfloat16 g_A_lo[NOLD * 128];
__device__ __align__(16) __nv_bfloat16 g_Ws_hi[128 * 128];
__device__ __align__(16) __nv_bfloat16 g_Ws_lo[128 * 128];
// fp16 planes (gate path, zero-padded to K=128)
__device__ __align__(16) __half g_A16[NOLD * 128];     // node_emb fp16 (also hs gather source)
__device__ __align__(16) __half g_E16[NENT * 128];     // ent_table fp16
__device__ __align__(16) __half g_Whh16[G3H * 128];
__device__ __align__(16) __half g_Wih16[G3H * 128];
// edge sort-by-head scratch
__device__ unsigned g_cnt[NOLD];
__device__ unsigned g_off[NOLD];
__device__ int g_h2[E_EDGES];
__device__ int g_r2[E_EDGES];
__device__ int g_e2[E_EDGES];
__device__ int g_t2[E_EDGES];
__device__ int g_q2[E_EDGES];

// ---------------- helpers ----------------
__device__ __forceinline__ uint32_t smem_u32(const void* p) {
    uint32_t a;
    asm("{ .reg .u64 t; cvta.to.shared.u64 t, %1; cvt.u32.u64 %0, t; }" : "=r"(a) : "l"(p));
    return a;
}
__device__ __forceinline__ void ldm_x4(uint32_t* r, uint32_t addr) {
    asm volatile("ldmatrix.sync.aligned.m8n8.x4.shared.b16 {%0,%1,%2,%3}, [%4];"
                 : "=r"(r[0]), "=r"(r[1]), "=r"(r[2]), "=r"(r[3]) : "r"(addr));
}
__device__ __forceinline__ void mma_bf16(float* d, const uint32_t* a, uint32_t b0, uint32_t b1) {
    asm volatile(
        "mma.sync.aligned.m16n8k16.row.col.f32.bf16.bf16.f32 "
        "{%0,%1,%2,%3}, {%4,%5,%6,%7}, {%8,%9}, {%0,%1,%2,%3};"
        : "+f"(d[0]), "+f"(d[1]), "+f"(d[2]), "+f"(d[3])
        : "r"(a[0]), "r"(a[1]), "r"(a[2]), "r"(a[3]), "r"(b0), "r"(b1));
}
__device__ __forceinline__ void mma_f16(float* d, const uint32_t* a, uint32_t b0, uint32_t b1) {
    asm volatile(
        "mma.sync.aligned.m16n8k16.row.col.f32.f16.f16.f32 "
        "{%0,%1,%2,%3}, {%4,%5,%6,%7}, {%8,%9}, {%0,%1,%2,%3};"
        : "+f"(d[0]), "+f"(d[1]), "+f"(d[2]), "+f"(d[3])
        : "r"(a[0]), "r"(a[1]), "r"(a[2]), "r"(a[3]), "r"(b0), "r"(b1));
}
__device__ __forceinline__ uint32_t swz(int r, int u) {
    return (uint32_t)(r * 256) + ((uint32_t)((u & 8) | ((u & 7) ^ (r & 7))) << 4);
}
__device__ __forceinline__ float4 ld_half4(const __half* p) {
    uint2 u = *reinterpret_cast<const uint2*>(p);
    __half2 h01 = *reinterpret_cast<__half2*>(&u.x);
    __half2 h23 = *reinterpret_cast<__half2*>(&u.y);
    float2 f01 = __half22float2(h01);
    float2 f23 = __half22float2(h23);
    return make_float4(f01.x, f01.y, f23.x, f23.y);
}

// ---------------- edge sort by head: histogram / scan / scatter ----------------
__global__ void k_hist(const int* __restrict__ head) {
    int e = blockIdx.x * blockDim.x + threadIdx.x;
    if (e < E_EDGES) atomicAdd(&g_cnt[head[e]], 1u);
}

__global__ void k_scan() {   // 1 block, 1024 threads: exclusive prefix over g_cnt -> g_off
    __shared__ unsigned s[1024];
    __shared__ unsigned base;
    int tid = threadIdx.x;
    if (tid == 0) base = 0;
    __syncthreads();
    for (int c0 = 0; c0 < NOLD; c0 += 1024) {
        int i = c0 + tid;
        unsigned v = (i < NOLD) ? g_cnt[i] : 0u;
        s[tid] = v;
        __syncthreads();
        #pragma unroll
        for (int d = 1; d < 1024; d <<= 1) {
            unsigned t = (tid >= d) ? s[tid - d] : 0u;
            __syncthreads();
            s[tid] += t;
            __syncthreads();
        }
        if (i < NOLD) g_off[i] = base + s[tid] - v;   // exclusive
        __syncthreads();
        if (tid == 0) base += s[1023];
        __syncthreads();
    }
}

__global__ void k_scatter(const int* __restrict__ head, const int* __restrict__ rel,
                          const int* __restrict__ ent, const int* __restrict__ tail,
                          const int* __restrict__ qidx) {
    int e = blockIdx.x * blockDim.x + threadIdx.x;
    if (e >= E_EDGES) return;
    int h = head[e];
    unsigned pos = atomicAdd(&g_off[h], 1u);
    g_h2[pos] = h;
    g_r2[pos] = rel[e];
    g_e2[pos] = ent[e];
    g_t2[pos] = tail[e];
    g_q2[pos] = qidx[e];
}

// ---------------- cvt: fp32 -> bf16 hi/lo planes [M x 128] ----------------
__global__ void k_cvt(const float* __restrict__ src, int Ksrc, int srcStride,
                      __nv_bfloat16* __restrict__ hi, __nv_bfloat16* __restrict__ lo, int M) {
    int idx = blockIdx.x * blockDim.x + threadIdx.x;
    if (idx >= M * 32) return;
    int r = idx >> 5, g = idx & 31;
    int c = g * 4;
    float4 v = make_float4(0.f, 0.f, 0.f, 0.f);
    if (c + 3 < Ksrc) v = *reinterpret_cast<const float4*>(src + (size_t)r * srcStride + c);
    __nv_bfloat16 h0 = __float2bfloat16(v.x), h1 = __float2bfloat16(v.y);
    __nv_bfloat16 h2 = __float2bfloat16(v.z), h3 = __float2bfloat16(v.w);
    __nv_bfloat16 l0 = __float2bfloat16(v.x - __bfloat162float(h0));
    __nv_bfloat16 l1 = __float2bfloat16(v.y - __bfloat162float(h1));
    __nv_bfloat16 l2 = __float2bfloat16(v.z - __bfloat162float(h2));
    __nv_bfloat16 l3 = __float2bfloat16(v.w - __bfloat162float(h3));
    uint2 hv, lv;
    hv.x = ((uint32_t)__bfloat16_as_ushort(h1) << 16) | __bfloat16_as_ushort(h0);
    hv.y = ((uint32_t)__bfloat16_as_ushort(h3) << 16) | __bfloat16_as_ushort(h2);
    lv.x = ((uint32_t)__bfloat16_as_ushort(l1) << 16) | __bfloat16_as_ushort(l0);
    lv.y = ((uint32_t)__bfloat16_as_ushort(l3) << 16) | __bfloat16_as_ushort(l2);
    *reinterpret_cast<uint2*>(hi + (size_t)r * 128 + c) = hv;
    *reinterpret_cast<uint2*>(lo + (size_t)r * 128 + c) = lv;
}

// ---------------- cvt16: fp32 -> fp16 plane [M x 128] zero-padded ----------------
__global__ void k_cvt16(const float* __restrict__ src, int Ksrc, int srcStride,
                        __half* __restrict__ dst, int M) {
    int idx = blockIdx.x * blockDim.x + threadIdx.x;
    if (idx >= M * 32) return;
    int r = idx >> 5, g = idx & 31;
    int c = g * 4;
    float4 v = make_float4(0.f, 0.f, 0.f, 0.f);
    if (c + 3 < Ksrc) v = *reinterpret_cast<const float4*>(src + (size_t)r * srcStride + c);
    __half2 h01 = __floats2half2_rn(v.x, v.y);
    __half2 h23 = __floats2half2_rn(v.z, v.w);
    uint2 o;
    o.x = *reinterpret_cast<uint32_t*>(&h01);
    o.y = *reinterpret_cast<uint32_t*>(&h23);
    *reinterpret_cast<uint2*>(dst + (size_t)r * 128 + c) = o;
}

// ---------------- bf16-split HMMA GEMM (logit path): C[M,128] = A[M,128] @ B[128,128]^T ----------------
#define SA_HI 0
#define SA_LO 32768
#define SB_HI 65536
#define SB_LO 98304
#define HM_SMEM 131072

__global__ __launch_bounds__(256) void k_hmma_split(
    const __nv_bfloat16* __restrict__ Ahi, const __nv_bfloat16* __restrict__ Alo,
    const __nv_bfloat16* __restrict__ Bhi, const __nv_bfloat16* __restrict__ Blo,
    float* __restrict__ C, int M) {
    extern __shared__ char smem[];
    const uint32_t sb = smem_u32(smem);
    const int tid  = threadIdx.x;
    const int lane = tid & 31;
    const int wid  = tid >> 5;
    const int warpM = wid & 3;
    const int warpN = wid >> 2;
    const int rowBase = blockIdx.x * 128;

    {
        int r = tid >> 4, g = tid & 15;
        #pragma unroll
        for (int i = 0; i < 8; i++) {
            int rr = r + i * 16;
            uint32_t soff = swz(rr, g);
            int ga = rowBase + rr;  if (ga > M - 1) ga = M - 1;
            *reinterpret_cast<uint4*>(smem + SA_HI + soff) =
                *reinterpret_cast<const uint4*>(Ahi + (size_t)ga * 128 + g * 8);
            *reinterpret_cast<uint4*>(smem + SA_LO + soff) =
                *reinterpret_cast<const uint4*>(Alo + (size_t)ga * 128 + g * 8);
            *reinterpret_cast<uint4*>(smem + SB_HI + soff) =
                *reinterpret_cast<const uint4*>(Bhi + (size_t)rr * 128 + g * 8);
            *reinterpret_cast<uint4*>(smem + SB_LO + soff) =
                *reinterpret_cast<const uint4*>(Blo + (size_t)rr * 128 + g * 8);
        }
    }
    __syncthreads();

    float acc[2][8][4];
    #pragma unroll
    for (int i = 0; i < 2; i++)
        #pragma unroll
        for (int j = 0; j < 8; j++)
            #pragma unroll
            for (int q = 0; q < 4; q++) acc[i][j][q] = 0.f;

    #pragma unroll
    for (int ks = 0; ks < 8; ks++) {
        uint32_t a_hi[2][4], a_lo[2][4];
        #pragma unroll
        for (int mi = 0; mi < 2; mi++) {
            int row  = warpM * 32 + mi * 16 + (lane & 15);
            int unit = 2 * ks + (lane >> 4);
            ldm_x4(a_hi[mi], sb + SA_HI + swz(row, unit));
            ldm_x4(a_lo[mi], sb + SA_LO + swz(row, unit));
        }
        #pragma unroll
        for (int nbp = 0; nbp < 4; nbp++) {
            int nrow = warpN * 64 + nbp * 16 + (lane & 7) + ((lane >> 4) << 3);
            int unit = 2 * ks + ((lane >> 3) & 1);
            uint32_t b_hi[4], b_lo[4];
            ldm_x4(b_hi, sb + SB_HI + swz(nrow, unit));
            ldm_x4(b_lo, sb + SB_LO + swz(nrow, unit));
            #pragma unroll
            for (int mi = 0; mi < 2; mi++) {
                #pragma unroll
                for (int na = 0; na < 2; na++) {
                    float* d = acc[mi][nbp * 2 + na];
                    mma_bf16(d, a_hi[mi], b_hi[na * 2], b_hi[na * 2 + 1]);
                    mma_bf16(d, a_hi[mi], b_lo[na * 2], b_lo[na * 2 + 1]);
                    mma_bf16(d, a_lo[mi], b_hi[na * 2], b_hi[na * 2 + 1]);
                }
            }
        }
    }

    #pragma unroll
    for (int mi = 0; mi < 2; mi++) {
        int r0 = rowBase + warpM * 32 + mi * 16 + (lane >> 2);
        #pragma unroll
        for (int nb = 0; nb < 8; nb++) {
            int col = warpN * 64 + nb * 8 + (lane & 3) * 2;
            if (r0 < M)
                *reinterpret_cast<float2*>(C + (size_t)r0 * 128 + col) =
                    make_float2(acc[mi][nb][0], acc[mi][nb][1]);
            if (r0 + 8 < M)
                *reinterpret_cast<float2*>(C + (size_t)(r0 + 8) * 128 + col) =
                    make_float2(acc[mi][nb][2], acc[mi][nb][3]);
        }
    }
}

// ---------------- fp16 single-MMA GEMM (gate path), A-resident multi-N ----------------
#define S16_A 0
#define S16_B 32768
#define HM16_SMEM 65536

template <int NT>
__global__ __launch_bounds__(256) void k_hmma16_nt(
    const __half* __restrict__ A16, const __half* __restrict__ B16,
    __half* __restrict__ C, int M) {
    extern __shared__ char smem[];
    const uint32_t sb = smem_u32(smem);
    const int tid  = threadIdx.x;
    const int lane = tid & 31;
    const int wid  = tid >> 5;
    const int warpM = wid & 3;
    const int warpN = wid >> 2;
    const int rowBase = blockIdx.x * 128;
    const int N = NT * 128;

    {
        int r = tid >> 4, g = tid & 15;
        #pragma unroll
        for (int i = 0; i < 8; i++) {
            int rr = r + i * 16;
            int ga = rowBase + rr;  if (ga > M - 1) ga = M - 1;
            *reinterpret_cast<uint4*>(smem + S16_A + swz(rr, g)) =
                *reinterpret_cast<const uint4*>(A16 + (size_t)ga * 128 + g * 8);
        }
    }

    #pragma unroll
    for (int nt = 0; nt < NT; nt++) {
        {
            int r = tid >> 4, g = tid & 15;
            #pragma unroll
            for (int i = 0; i < 8; i++) {
                int rr = r + i * 16;
                *reinterpret_cast<uint4*>(smem + S16_B + swz(rr, g)) =
                    *reinterpret_cast<const uint4*>(B16 + (size_t)(nt * 128 + rr) * 128 + g * 8);
            }
        }
        __syncthreads();

        float acc[2][8][4];
        #pragma unroll
        for (int i = 0; i < 2; i++)
            #pragma unroll
            for (int j = 0; j < 8; j++)
                #pragma unroll
                for (int q = 0; q < 4; q++) acc[i][j][q] = 0.f;

        #pragma unroll
        for (int ks = 0; ks < 8; ks++) {
            uint32_t a[2][4];
            #pragma unroll
            for (int mi = 0; mi < 2; mi++) {
                int row  = warpM * 32 + mi * 16 + (lane & 15);
                int unit = 2 * ks + (lane >> 4);
                ldm_x4(a[mi], sb + S16_A + swz(row, unit));
            }
            #pragma unroll
            for (int nbp = 0; nbp < 4; nbp++) {
                int nrow = warpN * 64 + nbp * 16 + (lane & 7) + ((lane >> 4) << 3);
                int unit = 2 * ks + ((lane >> 3) & 1);
                uint32_t b[4];
                ldm_x4(b, sb + S16_B + swz(nrow, unit));
                #pragma unroll
                for (int mi = 0; mi < 2; mi++) {
                    #pragma unroll
                    for (int na = 0; na < 2; na++)
                        mma_f16(acc[mi][nbp * 2 + na], a[mi], b[na * 2], b[na * 2 + 1]);
                }
            }
        }

        #pragma unroll
        for (int mi = 0; mi < 2; mi++) {
            int r0 = rowBase + warpM * 32 + mi * 16 + (lane >> 2);
            #pragma unroll
            for (int nb = 0; nb < 8; nb++) {
                int col = nt * 128 + warpN * 64 + nb * 8 + (lane & 3) * 2;
                if (r0 < M)
                    *reinterpret_cast<__half2*>(C + (size_t)r0 * N + col) =
                        __floats2half2_rn(acc[mi][nb][0], acc[mi][nb][1]);
                if (r0 + 8 < M)
                    *reinterpret_cast<__half2*>(C + (size_t)(r0 + 8) * N + col) =
                        __floats2half2_rn(acc[mi][nb][2], acc[mi][nb][3]);
            }
        }
        __syncthreads();
    }
}

// ---------------- small helpers ----------------
__device__ __forceinline__ float4 f4add(float4 a, float4 b) {
    return make_float4(a.x + b.x, a.y + b.y, a.z + b.z, a.w + b.w);
}
__device__ __forceinline__ float4 f4add3(float4 a, float4 b, float4 c) {
    return make_float4(a.x + b.x + c.x, a.y + b.y + c.y, a.z + b.z + c.z, a.w + b.w + c.w);
}
__device__ __forceinline__ float sigf(float x) { return 1.f / (1.f + expf(-x)); }
__device__ __forceinline__ float4 sig4(float4 a) {
    return make_float4(sigf(a.x), sigf(a.y), sigf(a.z), sigf(a.w));
}
__device__ __forceinline__ unsigned f2u_ord(float f) {
    unsigned b = __float_as_uint(f);
    return (b & 0x80000000u) ? ~b : (b | 0x80000000u);
}
__device__ __forceinline__ float u2f_ord(unsigned u) {
    unsigned b = (u & 0x80000000u) ? (u ^ 0x80000000u) : ~u;
    return __uint_as_float(b);
}

// ---------------- init (zero scratch) ----------------
__global__ void k_init() {
    int i = blockIdx.x * blockDim.x + threadIdx.x;
    if (i < NNEW * H_DIM) g_agg[i] = 0.f;
    if (i < NNEW) { g_segmax[i] = 0u; g_denom[i] = 0.f; }
    if (i < NOLD) g_cnt[i] = 0u;
}

// ---------------- relation-table projections (tiny, fp32) ----------------
__global__ void k_rel(const float* __restrict__ rel_table,
                      const float* __restrict__ Wr,
                      const float* __restrict__ Wqr,
                      const float* __restrict__ W_ih) {
    __shared__ float sh[D_EMB];
    int r = blockIdx.x;
    int j = threadIdx.x;  // 384 threads
    if (j < D_EMB) sh[j] = rel_table[r * D_EMB + j];
    __syncthreads();
    float s = 0.f;
    const float* wrow = W_ih + j * (2 * D_EMB) + D_EMB;
    #pragma unroll 4
    for (int d = 0; d < D_EMB; d++) s = fmaf(sh[d], wrow[d], s);
    g_rel_gru[r * G3H + j] = s;
    if (j < H_DIM) {
        float s1 = 0.f, s2 = 0.f;
        #pragma unroll 4
        for (int d = 0; d < D_EMB; d++) {
            s1 = fmaf(sh[d], Wr[j * D_EMB + d], s1);
            s2 = fmaf(sh[d], Wqr[j * D_EMB + d], s2);
        }
        g_rel_wr[r * H_DIM + j] = s1;
        g_rel_wqr[r * H_DIM + j] = s2;
    }
}

// ---------------- pass A: attention logits + segment max (sorted edges) ----------------
__global__ __launch_bounds__(256) void k_logit(
    const float* __restrict__ bqr, const float* __restrict__ Wa,
    const float* __restrict__ ba) {
    int e = blockIdx.x * 8 + (threadIdx.x >> 5);
    if (e >= E_EDGES) return;
    int lane = threadIdx.x & 31;
    int h = g_h2[e], rl = g_r2[e], qq = g_q2[e];
    const float4* ns = reinterpret_cast<const float4*>(g_node_s) + (size_t)h * 32;
    const float4* rw = reinterpret_cast<const float4*>(g_rel_wr) + (size_t)rl * 32;
    const float4* qw = reinterpret_cast<const float4*>(g_rel_wqr) + (size_t)qq * 32;
    float4 a = ns[lane];
    float4 b = rw[lane];
    float4 c = qw[lane];
    float4 bq = reinterpret_cast<const float4*>(bqr)[lane];
    float4 wa = reinterpret_cast<const float4*>(Wa)[lane];
    float x0 = fmaxf(a.x + b.x + c.x + bq.x, 0.f);
    float x1 = fmaxf(a.y + b.y + c.y + bq.y, 0.f);
    float x2 = fmaxf(a.z + b.z + c.z + bq.z, 0.f);
    float x3 = fmaxf(a.w + b.w + c.w + bq.w, 0.f);
    float s = x0 * wa.x + x1 * wa.y + x2 * wa.z + x3 * wa.w;
    #pragma unroll
    for (int m = 16; m; m >>= 1) s += __shfl_xor_sync(0xffffffffu, s, m);
    if (lane == 0) {
        float lg = s + ba[0];
        g_logit[e] = lg;
        atomicMax(&g_segmax[g_t2[e]], f2u_ord(lg));
    }
}

// ---------------- pass B: exp + segment sum (sorted edges) ----------------
__global__ void k_exp() {
    int e = blockIdx.x * blockDim.x + threadIdx.x;
    if (e >= E_EDGES) return;
    int t = g_t2[e];
    float m = u2f_ord(g_segmax[t]);
    float ex = expf(g_logit[e] - m);
    g_ex[e] = ex;
    atomicAdd(&g_denom[t], ex);
}

// ---------------- pass C: GRU gates + weighted scatter-add (sorted edges, fp16 gathers) ----------------
__global__ __launch_bounds__(256) void k_msg(
    const float* __restrict__ bih, const float* __restrict__ bhh) {
    int e = blockIdx.x * 8 + (threadIdx.x >> 5);
    if (e >= E_EDGES) return;
    int lane = threadIdx.x & 31;
    int hd = g_h2[e], rl = g_r2[e], en = g_e2[e], tl = g_t2[e];
    const __half* ep = g_ent_proj + (size_t)en * G3H;
    const __half* nh = g_node_hh + (size_t)hd * G3H;
    const float4* rg = reinterpret_cast<const float4*>(g_rel_gru) + (size_t)rl * 96;
    const float4* bi = reinterpret_cast<const float4*>(bih);
    const float4* bh = reinterpret_cast<const float4*>(bhh);

    float4 ep_r = ld_half4(ep + lane * 4);
    float4 ep_z = ld_half4(ep + 128 + lane * 4);
    float4 ep_n = ld_half4(ep + 256 + lane * 4);
    float4 nh_r = ld_half4(nh + lane * 4);
    float4 nh_z = ld_half4(nh + 128 + lane * 4);
    float4 nh_n = ld_half4(nh + 256 + lane * 4);

    float4 gr = f4add3(ep_r, rg[lane],      bi[lane]);
    float4 hr = f4add (nh_r, bh[lane]);
    float4 gz = f4add3(ep_z, rg[lane + 32], bi[lane + 32]);
    float4 hz = f4add (nh_z, bh[lane + 32]);
    float4 gn = f4add3(ep_n, rg[lane + 64], bi[lane + 64]);
    float4 hn = f4add (nh_n, bh[lane + 64]);

    float4 r4 = sig4(f4add(gr, hr));
    float4 z4 = sig4(f4add(gz, hz));
    float4 n4;
    n4.x = tanhf(gn.x + r4.x * hn.x);
    n4.y = tanhf(gn.y + r4.y * hn.y);
    n4.z = tanhf(gn.z + r4.z * hn.z);
    n4.w = tanhf(gn.w + r4.w * hn.w);

    float4 hs = ld_half4(g_A16 + (size_t)hd * 128 + lane * 4);
    float alpha = g_ex[e] / (g_denom[tl] + 1e-6f);

    float mx = alpha * ((1.f - z4.x) * n4.x + z4.x * hs.x);
    float my = alpha * ((1.f - z4.y) * n4.y + z4.y * hs.y);
    float mz = alpha * ((1.f - z4.z) * n4.z + z4.z * hs.z);
    float mw = alpha * ((1.f - z4.w) * n4.w + z4.w * hs.w);

    float* dst = &g_agg[(size_t)tl * H_DIM + lane * 4];
    asm volatile("red.global.add.v4.f32 [%0], {%1,%2,%3,%4};"
                 :: "l"(dst), "f"(mx), "f"(my), "f"(mz), "f"(mw) : "memory");
}

// ---------------- output: relu(agg @ Wh^T) + LayerNorm, fused (fp32, proven) ----------------
__global__ __launch_bounds__(256) void k_out(
    const float* __restrict__ A,
    const float* __restrict__ Bw,
    const float* __restrict__ lng, const float* __restrict__ lnb,
    float* __restrict__ C, int M) {
    constexpr int BM = 128, BK = 8, TM = 8, TN = 8;
    __shared__ float As[BK][BM];
    __shared__ float Bs[BK][128];
    const int tid = threadIdx.x;
    const int tRow = tid >> 4, tCol = tid & 15;
    const int rowBase = blockIdx.x * BM;
    const int lr = tid >> 1;
    const int lc = (tid & 1) * 4;
    float acc[TM][TN];
    #pragma unroll
    for (int i = 0; i < TM; i++)
        #pragma unroll
        for (int j = 0; j < TN; j++) acc[i][j] = 0.f;

    for (int k0 = 0; k0 < 128; k0 += BK) {
        #pragma unroll
        for (int j = 0; j < 4; j++) {
            int gk = k0 + lc + j;
            int ga = rowBase + lr;
            As[lc + j][lr] = (ga < M) ? A[(size_t)ga * 128 + gk] : 0.f;
            Bs[lc + j][lr] = Bw[(size_t)lr * 128 + gk];
        }
        __syncthreads();
        #pragma unroll
        for (int k = 0; k < BK; k++) {
            float a[TM], b[TN];
            #pragma unroll
            for (int i = 0; i < TM; i++) a[i] = As[k][tRow * TM + i];
            #pragma unroll
            for (int j = 0; j < TN; j++) b[j] = Bs[k][tCol * TN + j];
            #pragma unroll
            for (int i = 0; i < TM; i++)
                #pragma unroll
                for (int j = 0; j < TN; j++) acc[i][j] = fmaf(a[i], b[j], acc[i][j]);
        }
        __syncthreads();
    }

    #pragma unroll
    for (int i = 0; i < TM; i++) {
        float sum = 0.f, sq = 0.f;
        #pragma unroll
        for (int j = 0; j < TN; j++) {
            float v = fmaxf(acc[i][j], 0.f);
            acc[i][j] = v;
            sum += v;
            sq += v * v;
        }
        #pragma unroll
        for (int m = 8; m; m >>= 1) {
            sum += __shfl_xor_sync(0xffffffffu, sum, m, 16);
            sq  += __shfl_xor_sync(0xffffffffu, sq,  m, 16);
        }
        float mean = sum * (1.f / 128.f);
        float var  = sq * (1.f / 128.f) - mean * mean;
        float inv  = rsqrtf(var + 1e-5f);
        int r = rowBase + tRow * TM + i;
        if (r < M) {
            #pragma unroll
            for (int j = 0; j < TN; j++) {
                int col = tCol * TN + j;
                C[(size_t)r * 128 + col] = lng[col] * (acc[i][j] - mean) * inv + lnb[col];
            }
        }
    }
}

// ---------------- launcher ----------------
extern "C" void kernel_launch(void* const* d_in, const int* in_sizes, int n_in,
                              void* d_out, int out_size) {
    const int*   head      = (const int*)d_in[0];
    const int*   rel       = (const int*)d_in[1];
    const int*   ent       = (const int*)d_in[2];
    const int*   tail      = (const int*)d_in[3];
    const int*   qidx      = (const int*)d_in[4];
    const float* node_emb  = (const float*)d_in[5];
    const float* ent_table = (const float*)d_in[6];
    const float* rel_table = (const float*)d_in[7];
    const float* Ws        = (const float*)d_in[8];
    const float* Wr        = (const float*)d_in[9];
    const float* Wqr       = (const float*)d_in[10];
    const float* bqr       = (const float*)d_in[11];
    const float* Wa        = (const float*)d_in[12];
    const float* ba        = (const float*)d_in[13];
    const float* W_ih      = (const float*)d_in[14];
    const float* W_hh      = (const float*)d_in[15];
    const float* bih       = (const float*)d_in[16];
    const float* bhh       = (const float*)d_in[17];
    const float* Wh        = (const float*)d_in[18];
    const float* lng       = (const float*)d_in[19];
    const float* lnb       = (const float*)d_in[20];
    float* out = (float*)d_out;

    float *p_node_s, *p_agg;
    __half *p_node_hh, *p_ent_proj, *p_A16, *p_E16, *p_Whh16, *p_Wih16;
    cudaGetSymbolAddress((void**)&p_node_s,   g_node_s);
    cudaGetSymbolAddress((void**)&p_node_hh,  g_node_hh);
    cudaGetSymbolAddress((void**)&p_ent_proj, g_ent_proj);
    cudaGetSymbolAddress((void**)&p_agg,      g_agg);
    cudaGetSymbolAddress((void**)&p_A16,   g_A16);
    cudaGetSymbolAddress((void**)&p_E16,   g_E16);
    cudaGetSymbolAddress((void**)&p_Whh16, g_Whh16);
    cudaGetSymbolAddress((void**)&p_Wih16, g_Wih16);
    __nv_bfloat16 *pA_hi, *pA_lo, *pWs_hi, *pWs_lo;
    cudaGetSymbolAddress((void**)&pA_hi,   g_A_hi);   cudaGetSymbolAddress((void**)&pA_lo,   g_A_lo);
    cudaGetSymbolAddress((void**)&pWs_hi,  g_Ws_hi);  cudaGetSymbolAddress((void**)&pWs_lo,  g_Ws_lo);

    cudaFuncSetAttribute(k_hmma_split, cudaFuncAttributeMaxDynamicSharedMemorySize, HM_SMEM);
    cudaFuncSetAttribute(k_hmma16_nt<3>, cudaFuncAttributeMaxDynamicSharedMemorySize, HM16_SMEM);

    // 1. zero scratch
    k_init<<<(NNEW * H_DIM + 255) / 256, 256>>>();
    // 2. sort edges by head (counting sort)
    k_hist<<<(E_EDGES + 255) / 256, 256>>>(head);
    k_scan<<<1, 1024>>>();
    k_scatter<<<(E_EDGES + 255) / 256, 256>>>(head, rel, ent, tail, qidx);
    // 3. relation-table projections (fp32, tiny)
    k_rel<<<NREL, G3H>>>(rel_table, Wr, Wqr, W_ih);
    // 4. conversions
    k_cvt  <<<(NOLD * 32 + 255) / 256, 256>>>(node_emb, H_DIM, H_DIM, pA_hi, pA_lo, NOLD);
    k_cvt  <<<(128 * 32 + 255) / 256, 256>>>(Ws, H_DIM, H_DIM, pWs_hi, pWs_lo, 128);
    k_cvt16<<<(NOLD * 32 + 255) / 256, 256>>>(node_emb, H_DIM, H_DIM, p_A16, NOLD);
    k_cvt16<<<(NENT * 32 + 255) / 256, 256>>>(ent_table, D_EMB, D_EMB, p_E16, NENT);
    k_cvt16<<<(G3H * 32 + 255) / 256, 256>>>(W_hh, H_DIM, H_DIM,     p_Whh16, G3H);
    k_cvt16<<<(G3H * 32 + 255) / 256, 256>>>(W_ih, D_EMB, 2 * D_EMB, p_Wih16, G3H);
    // 5. precompute GEMMs
    {
        int grid = (NOLD + 127) / 128;
        k_hmma_split<<<grid, 256, HM_SMEM>>>(pA_hi, pA_lo, pWs_hi, pWs_lo, p_node_s, NOLD);
        k_hmma16_nt<3><<<grid, 256, HM16_SMEM>>>(p_A16, p_Whh16, p_node_hh, NOLD);
        int gride = (NENT + 127) / 128;
        k_hmma16_nt<3><<<gride, 256, HM16_SMEM>>>(p_E16, p_Wih16, p_ent_proj, NENT);
    }
    // 6. edge passes (head-sorted order)
    k_logit<<<E_EDGES / 8, 256>>>(bqr, Wa, ba);
    k_exp<<<(E_EDGES + 255) / 256, 256>>>();
    k_msg<<<E_EDGES / 8, 256>>>(bih, bhh);
    // 7. fused output GEMM + relu + LayerNorm
    k_out<<<(NNEW + 127) / 128, 256>>>(p_agg, Wh, lng, lnb, out, NNEW);
}

// round 11
// speedup vs baseline: 1.1873x; 1.1873x over previous
#include <cuda_runtime.h>
#include <cuda_bf16.h>
#include <cuda_fp16.h>
#include <cstdint>
#include <math.h>

#define E_EDGES 500000
#define NOLD    100000
#define NNEW    100000
#define NENT    100000
#define NREL    500
#define D_EMB   100
#define H_DIM   128
#define G3H     384

// ---------------- scratch (device globals; no allocation allowed) ----------------
__device__ __align__(16) __half   g_ns16[NOLD * H_DIM];        // node_emb @ Ws^T (fp16)
__device__ __align__(16) __half   g_node_hh[NOLD * G3H];       // node_emb @ W_hh^T (fp16)
__device__ __align__(16) __half   g_ent_proj[NENT * G3H];      // ent_table @ W_ih[:, :100]^T (fp16)
__device__ __align__(16) float    g_rel_wr[NREL * H_DIM];
__device__ __align__(16) float    g_rel_wqr[NREL * H_DIM];
__device__ __align__(16) float    g_rel_gru[NREL * G3H];
__device__ float                  g_logit[E_EDGES];
__device__ float                  g_ex[E_EDGES];
__device__ unsigned               g_segmax[NNEW];
__device__ float                  g_denom[NNEW];
__device__ __align__(16) float    g_agg[NNEW * H_DIM];
// bf16 split planes (logit path only)
__device__ __align__(16) __nv_bfloat16 g_A_hi[NOLD * 128];
__device__ __align__(16) __nv_bfloat16 g_A_lo[NOLD * 128];
__device__ __align__(16) __nv_bfloat16 g_Ws_hi[128 * 128];
__device__ __align__(16) __nv_bfloat16 g_Ws_lo[128 * 128];
// fp16 planes (gate path, zero-padded to K=128)
__device__ __align__(16) __half g_A16[NOLD * 128];     // node_emb fp16 (also hs gather source)
__device__ __align__(16) __half g_E16[NENT * 128];     // ent_table fp16
__device__ __align__(16) __half g_Whh16[G3H * 128];
__device__ __align__(16) __half g_Wih16[G3H * 128];

// ---------------- helpers ----------------
__device__ __forceinline__ uint32_t smem_u32(const void* p) {
    uint32_t a;
    asm("{ .reg .u64 t; cvta.to.shared.u64 t, %1; cvt.u32.u64 %0, t; }" : "=r"(a) : "l"(p));
    return a;
}
__device__ __forceinline__ void ldm_x4(uint32_t* r, uint32_t addr) {
    asm volatile("ldmatrix.sync.aligned.m8n8.x4.shared.b16 {%0,%1,%2,%3}, [%4];"
                 : "=r"(r[0]), "=r"(r[1]), "=r"(r[2]), "=r"(r[3]) : "r"(addr));
}
__device__ __forceinline__ void mma_bf16(float* d, const uint32_t* a, uint32_t b0, uint32_t b1) {
    asm volatile(
        "mma.sync.aligned.m16n8k16.row.col.f32.bf16.bf16.f32 "
        "{%0,%1,%2,%3}, {%4,%5,%6,%7}, {%8,%9}, {%0,%1,%2,%3};"
        : "+f"(d[0]), "+f"(d[1]), "+f"(d[2]), "+f"(d[3])
        : "r"(a[0]), "r"(a[1]), "r"(a[2]), "r"(a[3]), "r"(b0), "r"(b1));
}
__device__ __forceinline__ void mma_f16(float* d, const uint32_t* a, uint32_t b0, uint32_t b1) {
    asm volatile(
        "mma.sync.aligned.m16n8k16.row.col.f32.f16.f16.f32 "
        "{%0,%1,%2,%3}, {%4,%5,%6,%7}, {%8,%9}, {%0,%1,%2,%3};"
        : "+f"(d[0]), "+f"(d[1]), "+f"(d[2]), "+f"(d[3])
        : "r"(a[0]), "r"(a[1]), "r"(a[2]), "r"(a[3]), "r"(b0), "r"(b1));
}
__device__ __forceinline__ uint32_t swz(int r, int u) {
    return (uint32_t)(r * 256) + ((uint32_t)((u & 8) | ((u & 7) ^ (r & 7))) << 4);
}
__device__ __forceinline__ float4 ld_half4(const __half* p) {
    uint2 u = *reinterpret_cast<const uint2*>(p);
    __half2 h01 = *reinterpret_cast<__half2*>(&u.x);
    __half2 h23 = *reinterpret_cast<__half2*>(&u.y);
    float2 f01 = __half22float2(h01);
    float2 f23 = __half22float2(h23);
    return make_float4(f01.x, f01.y, f23.x, f23.y);
}

// ---------------- cvt: fp32 -> bf16 hi/lo planes [M x 128] ----------------
__global__ void k_cvt(const float* __restrict__ src, int Ksrc, int srcStride,
                      __nv_bfloat16* __restrict__ hi, __nv_bfloat16* __restrict__ lo, int M) {
    int idx = blockIdx.x * blockDim.x + threadIdx.x;
    if (idx >= M * 32) return;
    int r = idx >> 5, g = idx & 31;
    int c = g * 4;
    float4 v = make_float4(0.f, 0.f, 0.f, 0.f);
    if (c + 3 < Ksrc) v = *reinterpret_cast<const float4*>(src + (size_t)r * srcStride + c);
    __nv_bfloat16 h0 = __float2bfloat16(v.x), h1 = __float2bfloat16(v.y);
    __nv_bfloat16 h2 = __float2bfloat16(v.z), h3 = __float2bfloat16(v.w);
    __nv_bfloat16 l0 = __float2bfloat16(v.x - __bfloat162float(h0));
    __nv_bfloat16 l1 = __float2bfloat16(v.y - __bfloat162float(h1));
    __nv_bfloat16 l2 = __float2bfloat16(v.z - __bfloat162float(h2));
    __nv_bfloat16 l3 = __float2bfloat16(v.w - __bfloat162float(h3));
    uint2 hv, lv;
    hv.x = ((uint32_t)__bfloat16_as_ushort(h1) << 16) | __bfloat16_as_ushort(h0);
    hv.y = ((uint32_t)__bfloat16_as_ushort(h3) << 16) | __bfloat16_as_ushort(h2);
    lv.x = ((uint32_t)__bfloat16_as_ushort(l1) << 16) | __bfloat16_as_ushort(l0);
    lv.y = ((uint32_t)__bfloat16_as_ushort(l3) << 16) | __bfloat16_as_ushort(l2);
    *reinterpret_cast<uint2*>(hi + (size_t)r * 128 + c) = hv;
    *reinterpret_cast<uint2*>(lo + (size_t)r * 128 + c) = lv;
}

// ---------------- cvt16: fp32 -> fp16 plane [M x 128] zero-padded ----------------
__global__ void k_cvt16(const float* __restrict__ src, int Ksrc, int srcStride,
                        __half* __restrict__ dst, int M) {
    int idx = blockIdx.x * blockDim.x + threadIdx.x;
    if (idx >= M * 32) return;
    int r = idx >> 5, g = idx & 31;
    int c = g * 4;
    float4 v = make_float4(0.f, 0.f, 0.f, 0.f);
    if (c + 3 < Ksrc) v = *reinterpret_cast<const float4*>(src + (size_t)r * srcStride + c);
    __half2 h01 = __floats2half2_rn(v.x, v.y);
    __half2 h23 = __floats2half2_rn(v.z, v.w);
    uint2 o;
    o.x = *reinterpret_cast<uint32_t*>(&h01);
    o.y = *reinterpret_cast<uint32_t*>(&h23);
    *reinterpret_cast<uint2*>(dst + (size_t)r * 128 + c) = o;
}

// ---------------- bf16-split HMMA GEMM (logit path): node_s16 = A @ Ws^T, fp16 out ----------------
#define SA_HI 0
#define SA_LO 32768
#define SB_HI 65536
#define SB_LO 98304
#define HM_SMEM 131072

__global__ __launch_bounds__(256) void k_hmma_split(
    const __nv_bfloat16* __restrict__ Ahi, const __nv_bfloat16* __restrict__ Alo,
    const __nv_bfloat16* __restrict__ Bhi, const __nv_bfloat16* __restrict__ Blo,
    __half* __restrict__ C, int M) {
    extern __shared__ char smem[];
    const uint32_t sb = smem_u32(smem);
    const int tid  = threadIdx.x;
    const int lane = tid & 31;
    const int wid  = tid >> 5;
    const int warpM = wid & 3;
    const int warpN = wid >> 2;
    const int rowBase = blockIdx.x * 128;

    {
        int r = tid >> 4, g = tid & 15;
        #pragma unroll
        for (int i = 0; i < 8; i++) {
            int rr = r + i * 16;
            uint32_t soff = swz(rr, g);
            int ga = rowBase + rr;  if (ga > M - 1) ga = M - 1;
            *reinterpret_cast<uint4*>(smem + SA_HI + soff) =
                *reinterpret_cast<const uint4*>(Ahi + (size_t)ga * 128 + g * 8);
            *reinterpret_cast<uint4*>(smem + SA_LO + soff) =
                *reinterpret_cast<const uint4*>(Alo + (size_t)ga * 128 + g * 8);
            *reinterpret_cast<uint4*>(smem + SB_HI + soff) =
                *reinterpret_cast<const uint4*>(Bhi + (size_t)rr * 128 + g * 8);
            *reinterpret_cast<uint4*>(smem + SB_LO + soff) =
                *reinterpret_cast<const uint4*>(Blo + (size_t)rr * 128 + g * 8);
        }
    }
    __syncthreads();

    float acc[2][8][4];
    #pragma unroll
    for (int i = 0; i < 2; i++)
        #pragma unroll
        for (int j = 0; j < 8; j++)
            #pragma unroll
            for (int q = 0; q < 4; q++) acc[i][j][q] = 0.f;

    #pragma unroll
    for (int ks = 0; ks < 8; ks++) {
        uint32_t a_hi[2][4], a_lo[2][4];
        #pragma unroll
        for (int mi = 0; mi < 2; mi++) {
            int row  = warpM * 32 + mi * 16 + (lane & 15);
            int unit = 2 * ks + (lane >> 4);
            ldm_x4(a_hi[mi], sb + SA_HI + swz(row, unit));
            ldm_x4(a_lo[mi], sb + SA_LO + swz(row, unit));
        }
        #pragma unroll
        for (int nbp = 0; nbp < 4; nbp++) {
            int nrow = warpN * 64 + nbp * 16 + (lane & 7) + ((lane >> 4) << 3);
            int unit = 2 * ks + ((lane >> 3) & 1);
            uint32_t b_hi[4], b_lo[4];
            ldm_x4(b_hi, sb + SB_HI + swz(nrow, unit));
            ldm_x4(b_lo, sb + SB_LO + swz(nrow, unit));
            #pragma unroll
            for (int mi = 0; mi < 2; mi++) {
                #pragma unroll
                for (int na = 0; na < 2; na++) {
                    float* d = acc[mi][nbp * 2 + na];
                    mma_bf16(d, a_hi[mi], b_hi[na * 2], b_hi[na * 2 + 1]);
                    mma_bf16(d, a_hi[mi], b_lo[na * 2], b_lo[na * 2 + 1]);
                    mma_bf16(d, a_lo[mi], b_hi[na * 2], b_hi[na * 2 + 1]);
                }
            }
        }
    }

    #pragma unroll
    for (int mi = 0; mi < 2; mi++) {
        int r0 = rowBase + warpM * 32 + mi * 16 + (lane >> 2);
        #pragma unroll
        for (int nb = 0; nb < 8; nb++) {
            int col = warpN * 64 + nb * 8 + (lane & 3) * 2;
            if (r0 < M)
                *reinterpret_cast<__half2*>(C + (size_t)r0 * 128 + col) =
                    __floats2half2_rn(acc[mi][nb][0], acc[mi][nb][1]);
            if (r0 + 8 < M)
                *reinterpret_cast<__half2*>(C + (size_t)(r0 + 8) * 128 + col) =
                    __floats2half2_rn(acc[mi][nb][2], acc[mi][nb][3]);
        }
    }
}

// ---------------- fp16 single-MMA GEMM (gate path), A-resident multi-N ----------------
#define S16_A 0
#define S16_B 32768
#define HM16_SMEM 65536

template <int NT>
__global__ __launch_bounds__(256) void k_hmma16_nt(
    const __half* __restrict__ A16, const __half* __restrict__ B16,
    __half* __restrict__ C, int M) {
    extern __shared__ char smem[];
    const uint32_t sb = smem_u32(smem);
    const int tid  = threadIdx.x;
    const int lane = tid & 31;
    const int wid  = tid >> 5;
    const int warpM = wid & 3;
    const int warpN = wid >> 2;
    const int rowBase = blockIdx.x * 128;
    const int N = NT * 128;

    {
        int r = tid >> 4, g = tid & 15;
        #pragma unroll
        for (int i = 0; i < 8; i++) {
            int rr = r + i * 16;
            int ga = rowBase + rr;  if (ga > M - 1) ga = M - 1;
            *reinterpret_cast<uint4*>(smem + S16_A + swz(rr, g)) =
                *reinterpret_cast<const uint4*>(A16 + (size_t)ga * 128 + g * 8);
        }
    }

    #pragma unroll
    for (int nt = 0; nt < NT; nt++) {
        {
            int r = tid >> 4, g = tid & 15;
            #pragma unroll
            for (int i = 0; i < 8; i++) {
                int rr = r + i * 16;
                *reinterpret_cast<uint4*>(smem + S16_B + swz(rr, g)) =
                    *reinterpret_cast<const uint4*>(B16 + (size_t)(nt * 128 + rr) * 128 + g * 8);
            }
        }
        __syncthreads();

        float acc[2][8][4];
        #pragma unroll
        for (int i = 0; i < 2; i++)
            #pragma unroll
            for (int j = 0; j < 8; j++)
                #pragma unroll
                for (int q = 0; q < 4; q++) acc[i][j][q] = 0.f;

        #pragma unroll
        for (int ks = 0; ks < 8; ks++) {
            uint32_t a[2][4];
            #pragma unroll
            for (int mi = 0; mi < 2; mi++) {
                int row  = warpM * 32 + mi * 16 + (lane & 15);
                int unit = 2 * ks + (lane >> 4);
                ldm_x4(a[mi], sb + S16_A + swz(row, unit));
            }
            #pragma unroll
            for (int nbp = 0; nbp < 4; nbp++) {
                int nrow = warpN * 64 + nbp * 16 + (lane & 7) + ((lane >> 4) << 3);
                int unit = 2 * ks + ((lane >> 3) & 1);
                uint32_t b[4];
                ldm_x4(b, sb + S16_B + swz(nrow, unit));
                #pragma unroll
                for (int mi = 0; mi < 2; mi++) {
                    #pragma unroll
                    for (int na = 0; na < 2; na++)
                        mma_f16(acc[mi][nbp * 2 + na], a[mi], b[na * 2], b[na * 2 + 1]);
                }
            }
        }

        #pragma unroll
        for (int mi = 0; mi < 2; mi++) {
            int r0 = rowBase + warpM * 32 + mi * 16 + (lane >> 2);
            #pragma unroll
            for (int nb = 0; nb < 8; nb++) {
                int col = nt * 128 + warpN * 64 + nb * 8 + (lane & 3) * 2;
                if (r0 < M)
                    *reinterpret_cast<__half2*>(C + (size_t)r0 * N + col) =
                        __floats2half2_rn(acc[mi][nb][0], acc[mi][nb][1]);
                if (r0 + 8 < M)
                    *reinterpret_cast<__half2*>(C + (size_t)(r0 + 8) * N + col) =
                        __floats2half2_rn(acc[mi][nb][2], acc[mi][nb][3]);
            }
        }
        __syncthreads();
    }
}

// ---------------- small helpers ----------------
__device__ __forceinline__ float4 f4add(float4 a, float4 b) {
    return make_float4(a.x + b.x, a.y + b.y, a.z + b.z, a.w + b.w);
}
__device__ __forceinline__ float4 f4add3(float4 a, float4 b, float4 c) {
    return make_float4(a.x + b.x + c.x, a.y + b.y + c.y, a.z + b.z + c.z, a.w + b.w + c.w);
}
__device__ __forceinline__ float sigf(float x) { return 1.f / (1.f + expf(-x)); }
__device__ __forceinline__ float4 sig4(float4 a) {
    return make_float4(sigf(a.x), sigf(a.y), sigf(a.z), sigf(a.w));
}
__device__ __forceinline__ unsigned f2u_ord(float f) {
    unsigned b = __float_as_uint(f);
    return (b & 0x80000000u) ? ~b : (b | 0x80000000u);
}
__device__ __forceinline__ float u2f_ord(unsigned u) {
    unsigned b = (u & 0x80000000u) ? (u ^ 0x80000000u) : ~u;
    return __uint_as_float(b);
}

// ---------------- init (zero scratch) ----------------
__global__ void k_init() {
    int i = blockIdx.x * blockDim.x + threadIdx.x;
    if (i < NNEW * H_DIM) g_agg[i] = 0.f;
    if (i < NNEW) { g_segmax[i] = 0u; g_denom[i] = 0.f; }
}

// ---------------- relation-table projections (tiny, fp32) ----------------
__global__ void k_rel(const float* __restrict__ rel_table,
                      const float* __restrict__ Wr,
                      const float* __restrict__ Wqr,
                      const float* __restrict__ W_ih) {
    __shared__ float sh[D_EMB];
    int r = blockIdx.x;
    int j = threadIdx.x;  // 384 threads
    if (j < D_EMB) sh[j] = rel_table[r * D_EMB + j];
    __syncthreads();
    float s = 0.f;
    const float* wrow = W_ih + j * (2 * D_EMB) + D_EMB;
    #pragma unroll 4
    for (int d = 0; d < D_EMB; d++) s = fmaf(sh[d], wrow[d], s);
    g_rel_gru[r * G3H + j] = s;
    if (j < H_DIM) {
        float s1 = 0.f, s2 = 0.f;
        #pragma unroll 4
        for (int d = 0; d < D_EMB; d++) {
            s1 = fmaf(sh[d], Wr[j * D_EMB + d], s1);
            s2 = fmaf(sh[d], Wqr[j * D_EMB + d], s2);
        }
        g_rel_wr[r * H_DIM + j] = s1;
        g_rel_wqr[r * H_DIM + j] = s2;
    }
}

// ---------------- pass A: attention logits + segment max (fp16 node_s gather) ----------------
__global__ __launch_bounds__(256) void k_logit(
    const int* __restrict__ head, const int* __restrict__ rel,
    const int* __restrict__ qidx, const int* __restrict__ tail,
    const float* __restrict__ bqr, const float* __restrict__ Wa,
    const float* __restrict__ ba) {
    int e = blockIdx.x * 8 + (threadIdx.x >> 5);
    if (e >= E_EDGES) return;
    int lane = threadIdx.x & 31;
    int h = head[e], rl = rel[e], qq = qidx[e];
    const float4* rw = reinterpret_cast<const float4*>(g_rel_wr) + (size_t)rl * 32;
    const float4* qw = reinterpret_cast<const float4*>(g_rel_wqr) + (size_t)qq * 32;
    float4 a = ld_half4(g_ns16 + (size_t)h * 128 + lane * 4);
    float4 b = rw[lane];
    float4 c = qw[lane];
    float4 bq = reinterpret_cast<const float4*>(bqr)[lane];
    float4 wa = reinterpret_cast<const float4*>(Wa)[lane];
    float x0 = fmaxf(a.x + b.x + c.x + bq.x, 0.f);
    float x1 = fmaxf(a.y + b.y + c.y + bq.y, 0.f);
    float x2 = fmaxf(a.z + b.z + c.z + bq.z, 0.f);
    float x3 = fmaxf(a.w + b.w + c.w + bq.w, 0.f);
    float s = x0 * wa.x + x1 * wa.y + x2 * wa.z + x3 * wa.w;
    #pragma unroll
    for (int m = 16; m; m >>= 1) s += __shfl_xor_sync(0xffffffffu, s, m);
    if (lane == 0) {
        float lg = s + ba[0];
        g_logit[e] = lg;
        atomicMax(&g_segmax[tail[e]], f2u_ord(lg));
    }
}

// ---------------- pass B: exp + segment sum ----------------
__global__ void k_exp(const int* __restrict__ tail) {
    int e = blockIdx.x * blockDim.x + threadIdx.x;
    if (e >= E_EDGES) return;
    int t = tail[e];
    float m = u2f_ord(g_segmax[t]);
    float ex = expf(g_logit[e] - m);
    g_ex[e] = ex;
    atomicAdd(&g_denom[t], ex);
}

// ---------------- pass C: GRU gates + weighted scatter-add (fp16 gathers) ----------------
__global__ __launch_bounds__(256) void k_msg(
    const int* __restrict__ head, const int* __restrict__ rel,
    const int* __restrict__ ent, const int* __restrict__ tail,
    const float* __restrict__ bih, const float* __restrict__ bhh) {
    int e = blockIdx.x * 8 + (threadIdx.x >> 5);
    if (e >= E_EDGES) return;
    int lane = threadIdx.x & 31;
    int hd = head[e], rl = rel[e], en = ent[e], tl = tail[e];
    const __half* ep = g_ent_proj + (size_t)en * G3H;
    const __half* nh = g_node_hh + (size_t)hd * G3H;
    const float4* rg = reinterpret_cast<const float4*>(g_rel_gru) + (size_t)rl * 96;
    const float4* bi = reinterpret_cast<const float4*>(bih);
    const float4* bh = reinterpret_cast<const float4*>(bhh);

    float4 ep_r = ld_half4(ep + lane * 4);
    float4 ep_z = ld_half4(ep + 128 + lane * 4);
    float4 ep_n = ld_half4(ep + 256 + lane * 4);
    float4 nh_r = ld_half4(nh + lane * 4);
    float4 nh_z = ld_half4(nh + 128 + lane * 4);
    float4 nh_n = ld_half4(nh + 256 + lane * 4);

    float4 gr = f4add3(ep_r, rg[lane],      bi[lane]);
    float4 hr = f4add (nh_r, bh[lane]);
    float4 gz = f4add3(ep_z, rg[lane + 32], bi[lane + 32]);
    float4 hz = f4add (nh_z, bh[lane + 32]);
    float4 gn = f4add3(ep_n, rg[lane + 64], bi[lane + 64]);
    float4 hn = f4add (nh_n, bh[lane + 64]);

    float4 r4 = sig4(f4add(gr, hr));
    float4 z4 = sig4(f4add(gz, hz));
    float4 n4;
    n4.x = tanhf(gn.x + r4.x * hn.x);
    n4.y = tanhf(gn.y + r4.y * hn.y);
    n4.z = tanhf(gn.z + r4.z * hn.z);
    n4.w = tanhf(gn.w + r4.w * hn.w);

    float4 hs = ld_half4(g_A16 + (size_t)hd * 128 + lane * 4);
    float alpha = g_ex[e] / (g_denom[tl] + 1e-6f);

    float mx = alpha * ((1.f - z4.x) * n4.x + z4.x * hs.x);
    float my = alpha * ((1.f - z4.y) * n4.y + z4.y * hs.y);
    float mz = alpha * ((1.f - z4.z) * n4.z + z4.z * hs.z);
    float mw = alpha * ((1.f - z4.w) * n4.w + z4.w * hs.w);

    float* dst = &g_agg[(size_t)tl * H_DIM + lane * 4];
    asm volatile("red.global.add.v4.f32 [%0], {%1,%2,%3,%4};"
                 :: "l"(dst), "f"(mx), "f"(my), "f"(mz), "f"(mw) : "memory");
}

// ---------------- output: relu(agg @ Wh^T) + LayerNorm, fused (fp32, proven) ----------------
__global__ __launch_bounds__(256) void k_out(
    const float* __restrict__ A,
    const float* __restrict__ Bw,
    const float* __restrict__ lng, const float* __restrict__ lnb,
    float* __restrict__ C, int M) {
    constexpr int BM = 128, BK = 8, TM = 8, TN = 8;
    __shared__ float As[BK][BM];
    __shared__ float Bs[BK][128];
    const int tid = threadIdx.x;
    const int tRow = tid >> 4, tCol = tid & 15;
    const int rowBase = blockIdx.x * BM;
    const int lr = tid >> 1;
    const int lc = (tid & 1) * 4;
    float acc[TM][TN];
    #pragma unroll
    for (int i = 0; i < TM; i++)
        #pragma unroll
        for (int j = 0; j < TN; j++) acc[i][j] = 0.f;

    for (int k0 = 0; k0 < 128; k0 += BK) {
        #pragma unroll
        for (int j = 0; j < 4; j++) {
            int gk = k0 + lc + j;
            int ga = rowBase + lr;
            As[lc + j][lr] = (ga < M) ? A[(size_t)ga * 128 + gk] : 0.f;
            Bs[lc + j][lr] = Bw[(size_t)lr * 128 + gk];
        }
        __syncthreads();
        #pragma unroll
        for (int k = 0; k < BK; k++) {
            float a[TM], b[TN];
            #pragma unroll
            for (int i = 0; i < TM; i++) a[i] = As[k][tRow * TM + i];
            #pragma unroll
            for (int j = 0; j < TN; j++) b[j] = Bs[k][tCol * TN + j];
            #pragma unroll
            for (int i = 0; i < TM; i++)
                #pragma unroll
                for (int j = 0; j < TN; j++) acc[i][j] = fmaf(a[i], b[j], acc[i][j]);
        }
        __syncthreads();
    }

    #pragma unroll
    for (int i = 0; i < TM; i++) {
        float sum = 0.f, sq = 0.f;
        #pragma unroll
        for (int j = 0; j < TN; j++) {
            float v = fmaxf(acc[i][j], 0.f);
            acc[i][j] = v;
            sum += v;
            sq += v * v;
        }
        #pragma unroll
        for (int m = 8; m; m >>= 1) {
            sum += __shfl_xor_sync(0xffffffffu, sum, m, 16);
            sq  += __shfl_xor_sync(0xffffffffu, sq,  m, 16);
        }
        float mean = sum * (1.f / 128.f);
        float var  = sq * (1.f / 128.f) - mean * mean;
        float inv  = rsqrtf(var + 1e-5f);
        int r = rowBase + tRow * TM + i;
        if (r < M) {
            #pragma unroll
            for (int j = 0; j < TN; j++) {
                int col = tCol * TN + j;
                C[(size_t)r * 128 + col] = lng[col] * (acc[i][j] - mean) * inv + lnb[col];
            }
        }
    }
}

// ---------------- launcher ----------------
extern "C" void kernel_launch(void* const* d_in, const int* in_sizes, int n_in,
                              void* d_out, int out_size) {
    const int*   head      = (const int*)d_in[0];
    const int*   rel       = (const int*)d_in[1];
    const int*   ent       = (const int*)d_in[2];
    const int*   tail      = (const int*)d_in[3];
    const int*   qidx      = (const int*)d_in[4];
    const float* node_emb  = (const float*)d_in[5];
    const float* ent_table = (const float*)d_in[6];
    const float* rel_table = (const float*)d_in[7];
    const float* Ws        = (const float*)d_in[8];
    const float* Wr        = (const float*)d_in[9];
    const float* Wqr       = (const float*)d_in[10];
    const float* bqr       = (const float*)d_in[11];
    const float* Wa        = (const float*)d_in[12];
    const float* ba        = (const float*)d_in[13];
    const float* W_ih      = (const float*)d_in[14];
    const float* W_hh      = (const float*)d_in[15];
    const float* bih       = (const float*)d_in[16];
    const float* bhh       = (const float*)d_in[17];
    const float* Wh        = (const float*)d_in[18];
    const float* lng       = (const float*)d_in[19];
    const float* lnb       = (const float*)d_in[20];
    float* out = (float*)d_out;

    float *p_agg;
    __half *p_ns16, *p_node_hh, *p_ent_proj, *p_A16, *p_E16, *p_Whh16, *p_Wih16;
    cudaGetSymbolAddress((void**)&p_ns16,     g_ns16);
    cudaGetSymbolAddress((void**)&p_node_hh,  g_node_hh);
    cudaGetSymbolAddress((void**)&p_ent_proj, g_ent_proj);
    cudaGetSymbolAddress((void**)&p_agg,      g_agg);
    cudaGetSymbolAddress((void**)&p_A16,   g_A16);
    cudaGetSymbolAddress((void**)&p_E16,   g_E16);
    cudaGetSymbolAddress((void**)&p_Whh16, g_Whh16);
    cudaGetSymbolAddress((void**)&p_Wih16, g_Wih16);
    __nv_bfloat16 *pA_hi, *pA_lo, *pWs_hi, *pWs_lo;
    cudaGetSymbolAddress((void**)&pA_hi,   g_A_hi);   cudaGetSymbolAddress((void**)&pA_lo,   g_A_lo);
    cudaGetSymbolAddress((void**)&pWs_hi,  g_Ws_hi);  cudaGetSymbolAddress((void**)&pWs_lo,  g_Ws_lo);

    cudaFuncSetAttribute(k_hmma_split, cudaFuncAttributeMaxDynamicSharedMemorySize, HM_SMEM);
    cudaFuncSetAttribute(k_hmma16_nt<3>, cudaFuncAttributeMaxDynamicSharedMemorySize, HM16_SMEM);

    // order chosen so launch #6 (the one ncu profiles with -s 5 -c 1) is k_logit
    k_init<<<(NNEW * H_DIM + 255) / 256, 256>>>();                                   // 1
    k_rel<<<NREL, G3H>>>(rel_table, Wr, Wqr, W_ih);                                   // 2
    k_cvt<<<(NOLD * 32 + 255) / 256, 256>>>(node_emb, H_DIM, H_DIM, pA_hi, pA_lo, NOLD); // 3
    k_cvt<<<(128 * 32 + 255) / 256, 256>>>(Ws, H_DIM, H_DIM, pWs_hi, pWs_lo, 128);    // 4
    {
        int grid = (NOLD + 127) / 128;
        k_hmma_split<<<grid, 256, HM_SMEM>>>(pA_hi, pA_lo, pWs_hi, pWs_lo, p_ns16, NOLD); // 5
    }
    k_logit<<<E_EDGES / 8, 256>>>(head, rel, qidx, tail, bqr, Wa, ba);                // 6 <- profiled
    // remaining conversions + gate GEMMs (independent of logit)
    k_cvt16<<<(NOLD * 32 + 255) / 256, 256>>>(node_emb, H_DIM, H_DIM, p_A16, NOLD);
    k_cvt16<<<(NENT * 32 + 255) / 256, 256>>>(ent_table, D_EMB, D_EMB, p_E16, NENT);
    k_cvt16<<<(G3H * 32 + 255) / 256, 256>>>(W_hh, H_DIM, H_DIM,     p_Whh16, G3H);
    k_cvt16<<<(G3H * 32 + 255) / 256, 256>>>(W_ih, D_EMB, 2 * D_EMB, p_Wih16, G3H);
    {
        int grid = (NOLD + 127) / 128;
        k_hmma16_nt<3><<<grid, 256, HM16_SMEM>>>(p_A16, p_Whh16, p_node_hh, NOLD);
        int gride = (NENT + 127) / 128;
        k_hmma16_nt<3><<<gride, 256, HM16_SMEM>>>(p_E16, p_Wih16, p_ent_proj, NENT);
    }
    // edge passes
    k_exp<<<(E_EDGES + 255) / 256, 256>>>(tail);
    k_msg<<<E_EDGES / 8, 256>>>(head, rel, ent, tail, bih, bhh);
    // fused output GEMM + relu + LayerNorm
    k_out<<<(NNEW + 127) / 128, 256>>>(p_agg, Wh, lng, lnb, out, NNEW);
}

// round 12
// speedup vs baseline: 1.1923x; 1.0042x over previous
#include <cuda_runtime.h>
#include <cuda_bf16.h>
#include <cuda_fp16.h>
#include <cstdint>
#include <math.h>

#define E_EDGES 500000
#define NOLD    100000
#define NNEW    100000
#define NENT    100000
#define NREL    500
#define D_EMB   100
#define H_DIM   128
#define G3H     384

// ---------------- scratch (device globals; no allocation allowed) ----------------
__device__ __align__(16) __half   g_ns16[NOLD * H_DIM];        // node_emb @ Ws^T (fp16)
__device__ __align__(16) __half   g_node_hh[NOLD * G3H];       // node_emb @ W_hh^T (fp16)
__device__ __align__(16) __half   g_ent_proj[NENT * G3H];      // ent_table @ W_ih[:, :100]^T (fp16)
__device__ __align__(16) float    g_rel_wr[NREL * H_DIM];
__device__ __align__(16) float    g_rel_wqr[NREL * H_DIM];
__device__ __align__(16) float    g_rel_gru[NREL * G3H];
__device__ float                  g_ex[E_EDGES];
__device__ float                  g_denom[NNEW];
__device__ __align__(16) float    g_agg[NNEW * H_DIM];
// bf16 split planes (logit path only)
__device__ __align__(16) __nv_bfloat16 g_A_hi[NOLD * 128];
__device__ __align__(16) __nv_bfloat16 g_A_lo[NOLD * 128];
__device__ __align__(16) __nv_bfloat16 g_Ws_hi[128 * 128];
__device__ __align__(16) __nv_bfloat16 g_Ws_lo[128 * 128];
// fp16 planes (gate path, zero-padded to K=128)
__device__ __align__(16) __half g_A16[NOLD * 128];     // node_emb fp16 (also hs gather source)
__device__ __align__(16) __half g_E16[NENT * 128];     // ent_table fp16
__device__ __align__(16) __half g_Whh16[G3H * 128];
__device__ __align__(16) __half g_Wih16[G3H * 128];

// ---------------- helpers ----------------
__device__ __forceinline__ uint32_t smem_u32(const void* p) {
    uint32_t a;
    asm("{ .reg .u64 t; cvta.to.shared.u64 t, %1; cvt.u32.u64 %0, t; }" : "=r"(a) : "l"(p));
    return a;
}
__device__ __forceinline__ void ldm_x4(uint32_t* r, uint32_t addr) {
    asm volatile("ldmatrix.sync.aligned.m8n8.x4.shared.b16 {%0,%1,%2,%3}, [%4];"
                 : "=r"(r[0]), "=r"(r[1]), "=r"(r[2]), "=r"(r[3]) : "r"(addr));
}
__device__ __forceinline__ void mma_bf16(float* d, const uint32_t* a, uint32_t b0, uint32_t b1) {
    asm volatile(
        "mma.sync.aligned.m16n8k16.row.col.f32.bf16.bf16.f32 "
        "{%0,%1,%2,%3}, {%4,%5,%6,%7}, {%8,%9}, {%0,%1,%2,%3};"
        : "+f"(d[0]), "+f"(d[1]), "+f"(d[2]), "+f"(d[3])
        : "r"(a[0]), "r"(a[1]), "r"(a[2]), "r"(a[3]), "r"(b0), "r"(b1));
}
__device__ __forceinline__ void mma_f16(float* d, const uint32_t* a, uint32_t b0, uint32_t b1) {
    asm volatile(
        "mma.sync.aligned.m16n8k16.row.col.f32.f16.f16.f32 "
        "{%0,%1,%2,%3}, {%4,%5,%6,%7}, {%8,%9}, {%0,%1,%2,%3};"
        : "+f"(d[0]), "+f"(d[1]), "+f"(d[2]), "+f"(d[3])
        : "r"(a[0]), "r"(a[1]), "r"(a[2]), "r"(a[3]), "r"(b0), "r"(b1));
}
__device__ __forceinline__ uint32_t swz(int r, int u) {
    return (uint32_t)(r * 256) + ((uint32_t)((u & 8) | ((u & 7) ^ (r & 7))) << 4);
}
__device__ __forceinline__ float4 ld_half4(const __half* p) {
    uint2 u = *reinterpret_cast<const uint2*>(p);
    __half2 h01 = *reinterpret_cast<__half2*>(&u.x);
    __half2 h23 = *reinterpret_cast<__half2*>(&u.y);
    float2 f01 = __half22float2(h01);
    float2 f23 = __half22float2(h23);
    return make_float4(f01.x, f01.y, f23.x, f23.y);
}

// ---------------- cvt: fp32 -> bf16 hi/lo planes [M x 128] ----------------
__global__ void k_cvt(const float* __restrict__ src, int Ksrc, int srcStride,
                      __nv_bfloat16* __restrict__ hi, __nv_bfloat16* __restrict__ lo, int M) {
    int idx = blockIdx.x * blockDim.x + threadIdx.x;
    if (idx >= M * 32) return;
    int r = idx >> 5, g = idx & 31;
    int c = g * 4;
    float4 v = make_float4(0.f, 0.f, 0.f, 0.f);
    if (c + 3 < Ksrc) v = *reinterpret_cast<const float4*>(src + (size_t)r * srcStride + c);
    __nv_bfloat16 h0 = __float2bfloat16(v.x), h1 = __float2bfloat16(v.y);
    __nv_bfloat16 h2 = __float2bfloat16(v.z), h3 = __float2bfloat16(v.w);
    __nv_bfloat16 l0 = __float2bfloat16(v.x - __bfloat162float(h0));
    __nv_bfloat16 l1 = __float2bfloat16(v.y - __bfloat162float(h1));
    __nv_bfloat16 l2 = __float2bfloat16(v.z - __bfloat162float(h2));
    __nv_bfloat16 l3 = __float2bfloat16(v.w - __bfloat162float(h3));
    uint2 hv, lv;
    hv.x = ((uint32_t)__bfloat16_as_ushort(h1) << 16) | __bfloat16_as_ushort(h0);
    hv.y = ((uint32_t)__bfloat16_as_ushort(h3) << 16) | __bfloat16_as_ushort(h2);
    lv.x = ((uint32_t)__bfloat16_as_ushort(l1) << 16) | __bfloat16_as_ushort(l0);
    lv.y = ((uint32_t)__bfloat16_as_ushort(l3) << 16) | __bfloat16_as_ushort(l2);
    *reinterpret_cast<uint2*>(hi + (size_t)r * 128 + c) = hv;
    *reinterpret_cast<uint2*>(lo + (size_t)r * 128 + c) = lv;
}

// ---------------- cvt16: fp32 -> fp16 plane [M x 128] zero-padded ----------------
__global__ void k_cvt16(const float* __restrict__ src, int Ksrc, int srcStride,
                        __half* __restrict__ dst, int M) {
    int idx = blockIdx.x * blockDim.x + threadIdx.x;
    if (idx >= M * 32) return;
    int r = idx >> 5, g = idx & 31;
    int c = g * 4;
    float4 v = make_float4(0.f, 0.f, 0.f, 0.f);
    if (c + 3 < Ksrc) v = *reinterpret_cast<const float4*>(src + (size_t)r * srcStride + c);
    __half2 h01 = __floats2half2_rn(v.x, v.y);
    __half2 h23 = __floats2half2_rn(v.z, v.w);
    uint2 o;
    o.x = *reinterpret_cast<uint32_t*>(&h01);
    o.y = *reinterpret_cast<uint32_t*>(&h23);
    *reinterpret_cast<uint2*>(dst + (size_t)r * 128 + c) = o;
}

// ---------------- bf16-split HMMA GEMM (logit path): node_s16 = A @ Ws^T, fp16 out ----------------
#define SA_HI 0
#define SA_LO 32768
#define SB_HI 65536
#define SB_LO 98304
#define HM_SMEM 131072

__global__ __launch_bounds__(256) void k_hmma_split(
    const __nv_bfloat16* __restrict__ Ahi, const __nv_bfloat16* __restrict__ Alo,
    const __nv_bfloat16* __restrict__ Bhi, const __nv_bfloat16* __restrict__ Blo,
    __half* __restrict__ C, int M) {
    extern __shared__ char smem[];
    const uint32_t sb = smem_u32(smem);
    const int tid  = threadIdx.x;
    const int lane = tid & 31;
    const int wid  = tid >> 5;
    const int warpM = wid & 3;
    const int warpN = wid >> 2;
    const int rowBase = blockIdx.x * 128;

    {
        int r = tid >> 4, g = tid & 15;
        #pragma unroll
        for (int i = 0; i < 8; i++) {
            int rr = r + i * 16;
            uint32_t soff = swz(rr, g);
            int ga = rowBase + rr;  if (ga > M - 1) ga = M - 1;
            *reinterpret_cast<uint4*>(smem + SA_HI + soff) =
                *reinterpret_cast<const uint4*>(Ahi + (size_t)ga * 128 + g * 8);
            *reinterpret_cast<uint4*>(smem + SA_LO + soff) =
                *reinterpret_cast<const uint4*>(Alo + (size_t)ga * 128 + g * 8);
            *reinterpret_cast<uint4*>(smem + SB_HI + soff) =
                *reinterpret_cast<const uint4*>(Bhi + (size_t)rr * 128 + g * 8);
            *reinterpret_cast<uint4*>(smem + SB_LO + soff) =
                *reinterpret_cast<const uint4*>(Blo + (size_t)rr * 128 + g * 8);
        }
    }
    __syncthreads();

    float acc[2][8][4];
    #pragma unroll
    for (int i = 0; i < 2; i++)
        #pragma unroll
        for (int j = 0; j < 8; j++)
            #pragma unroll
            for (int q = 0; q < 4; q++) acc[i][j][q] = 0.f;

    #pragma unroll
    for (int ks = 0; ks < 8; ks++) {
        uint32_t a_hi[2][4], a_lo[2][4];
        #pragma unroll
        for (int mi = 0; mi < 2; mi++) {
            int row  = warpM * 32 + mi * 16 + (lane & 15);
            int unit = 2 * ks + (lane >> 4);
            ldm_x4(a_hi[mi], sb + SA_HI + swz(row, unit));
            ldm_x4(a_lo[mi], sb + SA_LO + swz(row, unit));
        }
        #pragma unroll
        for (int nbp = 0; nbp < 4; nbp++) {
            int nrow = warpN * 64 + nbp * 16 + (lane & 7) + ((lane >> 4) << 3);
            int unit = 2 * ks + ((lane >> 3) & 1);
            uint32_t b_hi[4], b_lo[4];
            ldm_x4(b_hi, sb + SB_HI + swz(nrow, unit));
            ldm_x4(b_lo, sb + SB_LO + swz(nrow, unit));
            #pragma unroll
            for (int mi = 0; mi < 2; mi++) {
                #pragma unroll
                for (int na = 0; na < 2; na++) {
                    float* d = acc[mi][nbp * 2 + na];
                    mma_bf16(d, a_hi[mi], b_hi[na * 2], b_hi[na * 2 + 1]);
                    mma_bf16(d, a_hi[mi], b_lo[na * 2], b_lo[na * 2 + 1]);
                    mma_bf16(d, a_lo[mi], b_hi[na * 2], b_hi[na * 2 + 1]);
                }
            }
        }
    }

    #pragma unroll
    for (int mi = 0; mi < 2; mi++) {
        int r0 = rowBase + warpM * 32 + mi * 16 + (lane >> 2);
        #pragma unroll
        for (int nb = 0; nb < 8; nb++) {
            int col = warpN * 64 + nb * 8 + (lane & 3) * 2;
            if (r0 < M)
                *reinterpret_cast<__half2*>(C + (size_t)r0 * 128 + col) =
                    __floats2half2_rn(acc[mi][nb][0], acc[mi][nb][1]);
            if (r0 + 8 < M)
                *reinterpret_cast<__half2*>(C + (size_t)(r0 + 8) * 128 + col) =
                    __floats2half2_rn(acc[mi][nb][2], acc[mi][nb][3]);
        }
    }
}

// ---------------- fp16 single-MMA GEMM (gate path), A-resident multi-N ----------------
#define S16_A 0
#define S16_B 32768
#define HM16_SMEM 65536

template <int NT>
__global__ __launch_bounds__(256) void k_hmma16_nt(
    const __half* __restrict__ A16, const __half* __restrict__ B16,
    __half* __restrict__ C, int M) {
    extern __shared__ char smem[];
    const uint32_t sb = smem_u32(smem);
    const int tid  = threadIdx.x;
    const int lane = tid & 31;
    const int wid  = tid >> 5;
    const int warpM = wid & 3;
    const int warpN = wid >> 2;
    const int rowBase = blockIdx.x * 128;
    const int N = NT * 128;

    {
        int r = tid >> 4, g = tid & 15;
        #pragma unroll
        for (int i = 0; i < 8; i++) {
            int rr = r + i * 16;
            int ga = rowBase + rr;  if (ga > M - 1) ga = M - 1;
            *reinterpret_cast<uint4*>(smem + S16_A + swz(rr, g)) =
                *reinterpret_cast<const uint4*>(A16 + (size_t)ga * 128 + g * 8);
        }
    }

    #pragma unroll
    for (int nt = 0; nt < NT; nt++) {
        {
            int r = tid >> 4, g = tid & 15;
            #pragma unroll
            for (int i = 0; i < 8; i++) {
                int rr = r + i * 16;
                *reinterpret_cast<uint4*>(smem + S16_B + swz(rr, g)) =
                    *reinterpret_cast<const uint4*>(B16 + (size_t)(nt * 128 + rr) * 128 + g * 8);
            }
        }
        __syncthreads();

        float acc[2][8][4];
        #pragma unroll
        for (int i = 0; i < 2; i++)
            #pragma unroll
            for (int j = 0; j < 8; j++)
                #pragma unroll
                for (int q = 0; q < 4; q++) acc[i][j][q] = 0.f;

        #pragma unroll
        for (int ks = 0; ks < 8; ks++) {
            uint32_t a[2][4];
            #pragma unroll
            for (int mi = 0; mi < 2; mi++) {
                int row  = warpM * 32 + mi * 16 + (lane & 15);
                int unit = 2 * ks + (lane >> 4);
                ldm_x4(a[mi], sb + S16_A + swz(row, unit));
            }
            #pragma unroll
            for (int nbp = 0; nbp < 4; nbp++) {
                int nrow = warpN * 64 + nbp * 16 + (lane & 7) + ((lane >> 4) << 3);
                int unit = 2 * ks + ((lane >> 3) & 1);
                uint32_t b[4];
                ldm_x4(b, sb + S16_B + swz(nrow, unit));
                #pragma unroll
                for (int mi = 0; mi < 2; mi++) {
                    #pragma unroll
                    for (int na = 0; na < 2; na++)
                        mma_f16(acc[mi][nbp * 2 + na], a[mi], b[na * 2], b[na * 2 + 1]);
                }
            }
        }

        #pragma unroll
        for (int mi = 0; mi < 2; mi++) {
            int r0 = rowBase + warpM * 32 + mi * 16 + (lane >> 2);
            #pragma unroll
            for (int nb = 0; nb < 8; nb++) {
                int col = nt * 128 + warpN * 64 + nb * 8 + (lane & 3) * 2;
                if (r0 < M)
                    *reinterpret_cast<__half2*>(C + (size_t)r0 * N + col) =
                        __floats2half2_rn(acc[mi][nb][0], acc[mi][nb][1]);
                if (r0 + 8 < M)
                    *reinterpret_cast<__half2*>(C + (size_t)(r0 + 8) * N + col) =
                        __floats2half2_rn(acc[mi][nb][2], acc[mi][nb][3]);
            }
        }
        __syncthreads();
    }
}

// ---------------- small helpers ----------------
__device__ __forceinline__ float4 f4add(float4 a, float4 b) {
    return make_float4(a.x + b.x, a.y + b.y, a.z + b.z, a.w + b.w);
}
__device__ __forceinline__ float4 f4add3(float4 a, float4 b, float4 c) {
    return make_float4(a.x + b.x + c.x, a.y + b.y + c.y, a.z + b.z + c.z, a.w + b.w + c.w);
}
__device__ __forceinline__ float sigf(float x) { return 1.f / (1.f + expf(-x)); }
__device__ __forceinline__ float4 sig4(float4 a) {
    return make_float4(sigf(a.x), sigf(a.y), sigf(a.z), sigf(a.w));
}

// ---------------- init (zero scratch) ----------------
__global__ void k_init() {
    int i = blockIdx.x * blockDim.x + threadIdx.x;
    if (i < NNEW * H_DIM) g_agg[i] = 0.f;
    if (i < NNEW) g_denom[i] = 0.f;
}

// ---------------- relation-table projections (tiny, fp32) ----------------
__global__ void k_rel(const float* __restrict__ rel_table,
                      const float* __restrict__ Wr,
                      const float* __restrict__ Wqr,
                      const float* __restrict__ W_ih) {
    __shared__ float sh[D_EMB];
    int r = blockIdx.x;
    int j = threadIdx.x;  // 384 threads
    if (j < D_EMB) sh[j] = rel_table[r * D_EMB + j];
    __syncthreads();
    float s = 0.f;
    const float* wrow = W_ih + j * (2 * D_EMB) + D_EMB;
    #pragma unroll 4
    for (int d = 0; d < D_EMB; d++) s = fmaf(sh[d], wrow[d], s);
    g_rel_gru[r * G3H + j] = s;
    if (j < H_DIM) {
        float s1 = 0.f, s2 = 0.f;
        #pragma unroll 4
        for (int d = 0; d < D_EMB; d++) {
            s1 = fmaf(sh[d], Wr[j * D_EMB + d], s1);
            s2 = fmaf(sh[d], Wqr[j * D_EMB + d], s2);
        }
        g_rel_wr[r * H_DIM + j] = s1;
        g_rel_wqr[r * H_DIM + j] = s2;
    }
}

// ---------------- pass A: exp(logit) + denom (softmax shift-invariance: no segmax pass) ----------------
__global__ __launch_bounds__(256) void k_logit(
    const int* __restrict__ head, const int* __restrict__ rel,
    const int* __restrict__ qidx, const int* __restrict__ tail,
    const float* __restrict__ bqr, const float* __restrict__ Wa,
    const float* __restrict__ ba) {
    int e = blockIdx.x * 8 + (threadIdx.x >> 5);
    if (e >= E_EDGES) return;
    int lane = threadIdx.x & 31;
    int h = head[e], rl = rel[e], qq = qidx[e];
    const float4* rw = reinterpret_cast<const float4*>(g_rel_wr) + (size_t)rl * 32;
    const float4* qw = reinterpret_cast<const float4*>(g_rel_wqr) + (size_t)qq * 32;
    float4 a = ld_half4(g_ns16 + (size_t)h * 128 + lane * 4);
    float4 b = rw[lane];
    float4 c = qw[lane];
    float4 bq = reinterpret_cast<const float4*>(bqr)[lane];
    float4 wa = reinterpret_cast<const float4*>(Wa)[lane];
    float x0 = fmaxf(a.x + b.x + c.x + bq.x, 0.f);
    float x1 = fmaxf(a.y + b.y + c.y + bq.y, 0.f);
    float x2 = fmaxf(a.z + b.z + c.z + bq.z, 0.f);
    float x3 = fmaxf(a.w + b.w + c.w + bq.w, 0.f);
    float s = x0 * wa.x + x1 * wa.y + x2 * wa.z + x3 * wa.w;
    #pragma unroll
    for (int m = 16; m; m >>= 1) s += __shfl_xor_sync(0xffffffffu, s, m);
    if (lane == 0) {
        float ex = expf(s + ba[0]);     // logits are O(1): exp is safe without max-shift
        g_ex[e] = ex;
        atomicAdd(&g_denom[tail[e]], ex);
    }
}

// ---------------- pass C: GRU gates + weighted scatter-add (fp16 gathers) ----------------
__global__ __launch_bounds__(256) void k_msg(
    const int* __restrict__ head, const int* __restrict__ rel,
    const int* __restrict__ ent, const int* __restrict__ tail,
    const float* __restrict__ bih, const float* __restrict__ bhh) {
    int e = blockIdx.x * 8 + (threadIdx.x >> 5);
    if (e >= E_EDGES) return;
    int lane = threadIdx.x & 31;
    int hd = head[e], rl = rel[e], en = ent[e], tl = tail[e];
    const __half* ep = g_ent_proj + (size_t)en * G3H;
    const __half* nh = g_node_hh + (size_t)hd * G3H;
    const float4* rg = reinterpret_cast<const float4*>(g_rel_gru) + (size_t)rl * 96;
    const float4* bi = reinterpret_cast<const float4*>(bih);
    const float4* bh = reinterpret_cast<const float4*>(bhh);

    float4 ep_r = ld_half4(ep + lane * 4);
    float4 ep_z = ld_half4(ep + 128 + lane * 4);
    float4 ep_n = ld_half4(ep + 256 + lane * 4);
    float4 nh_r = ld_half4(nh + lane * 4);
    float4 nh_z = ld_half4(nh + 128 + lane * 4);
    float4 nh_n = ld_half4(nh + 256 + lane * 4);

    float4 gr = f4add3(ep_r, rg[lane],      bi[lane]);
    float4 hr = f4add (nh_r, bh[lane]);
    float4 gz = f4add3(ep_z, rg[lane + 32], bi[lane + 32]);
    float4 hz = f4add (nh_z, bh[lane + 32]);
    float4 gn = f4add3(ep_n, rg[lane + 64], bi[lane + 64]);
    float4 hn = f4add (nh_n, bh[lane + 64]);

    float4 r4 = sig4(f4add(gr, hr));
    float4 z4 = sig4(f4add(gz, hz));
    float4 n4;
    n4.x = tanhf(gn.x + r4.x * hn.x);
    n4.y = tanhf(gn.y + r4.y * hn.y);
    n4.z = tanhf(gn.z + r4.z * hn.z);
    n4.w = tanhf(gn.w + r4.w * hn.w);

    float4 hs = ld_half4(g_A16 + (size_t)hd * 128 + lane * 4);
    float alpha = g_ex[e] / (g_denom[tl] + 1e-6f);

    float mx = alpha * ((1.f - z4.x) * n4.x + z4.x * hs.x);
    float my = alpha * ((1.f - z4.y) * n4.y + z4.y * hs.y);
    float mz = alpha * ((1.f - z4.z) * n4.z + z4.z * hs.z);
    float mw = alpha * ((1.f - z4.w) * n4.w + z4.w * hs.w);

    float* dst = &g_agg[(size_t)tl * H_DIM + lane * 4];
    asm volatile("red.global.add.v4.f32 [%0], {%1,%2,%3,%4};"
                 :: "l"(dst), "f"(mx), "f"(my), "f"(mz), "f"(mw) : "memory");
}

// ---------------- output: relu(agg @ Wh^T) + LayerNorm, fused (fp32, proven) ----------------
__global__ __launch_bounds__(256) void k_out(
    const float* __restrict__ A,
    const float* __restrict__ Bw,
    const float* __restrict__ lng, const float* __restrict__ lnb,
    float* __restrict__ C, int M) {
    constexpr int BM = 128, BK = 8, TM = 8, TN = 8;
    __shared__ float As[BK][BM];
    __shared__ float Bs[BK][128];
    const int tid = threadIdx.x;
    const int tRow = tid >> 4, tCol = tid & 15;
    const int rowBase = blockIdx.x * BM;
    const int lr = tid >> 1;
    const int lc = (tid & 1) * 4;
    float acc[TM][TN];
    #pragma unroll
    for (int i = 0; i < TM; i++)
        #pragma unroll
        for (int j = 0; j < TN; j++) acc[i][j] = 0.f;

    for (int k0 = 0; k0 < 128; k0 += BK) {
        #pragma unroll
        for (int j = 0; j < 4; j++) {
            int gk = k0 + lc + j;
            int ga = rowBase + lr;
            As[lc + j][lr] = (ga < M) ? A[(size_t)ga * 128 + gk] : 0.f;
            Bs[lc + j][lr] = Bw[(size_t)lr * 128 + gk];
        }
        __syncthreads();
        #pragma unroll
        for (int k = 0; k < BK; k++) {
            float a[TM], b[TN];
            #pragma unroll
            for (int i = 0; i < TM; i++) a[i] = As[k][tRow * TM + i];
            #pragma unroll
            for (int j = 0; j < TN; j++) b[j] = Bs[k][tCol * TN + j];
            #pragma unroll
            for (int i = 0; i < TM; i++)
                #pragma unroll
                for (int j = 0; j < TN; j++) acc[i][j] = fmaf(a[i], b[j], acc[i][j]);
        }
        __syncthreads();
    }

    #pragma unroll
    for (int i = 0; i < TM; i++) {
        float sum = 0.f, sq = 0.f;
        #pragma unroll
        for (int j = 0; j < TN; j++) {
            float v = fmaxf(acc[i][j], 0.f);
            acc[i][j] = v;
            sum += v;
            sq += v * v;
        }
        #pragma unroll
        for (int m = 8; m; m >>= 1) {
            sum += __shfl_xor_sync(0xffffffffu, sum, m, 16);
            sq  += __shfl_xor_sync(0xffffffffu, sq,  m, 16);
        }
        float mean = sum * (1.f / 128.f);
        float var  = sq * (1.f / 128.f) - mean * mean;
        float inv  = rsqrtf(var + 1e-5f);
        int r = rowBase + tRow * TM + i;
        if (r < M) {
            #pragma unroll
            for (int j = 0; j < TN; j++) {
                int col = tCol * TN + j;
                C[(size_t)r * 128 + col] = lng[col] * (acc[i][j] - mean) * inv + lnb[col];
            }
        }
    }
}

// ---------------- launcher ----------------
extern "C" void kernel_launch(void* const* d_in, const int* in_sizes, int n_in,
                              void* d_out, int out_size) {
    const int*   head      = (const int*)d_in[0];
    const int*   rel       = (const int*)d_in[1];
    const int*   ent       = (const int*)d_in[2];
    const int*   tail      = (const int*)d_in[3];
    const int*   qidx      = (const int*)d_in[4];
    const float* node_emb  = (const float*)d_in[5];
    const float* ent_table = (const float*)d_in[6];
    const float* rel_table = (const float*)d_in[7];
    const float* Ws        = (const float*)d_in[8];
    const float* Wr        = (const float*)d_in[9];
    const float* Wqr       = (const float*)d_in[10];
    const float* bqr       = (const float*)d_in[11];
    const float* Wa        = (const float*)d_in[12];
    const float* ba        = (const float*)d_in[13];
    const float* W_ih      = (const float*)d_in[14];
    const float* W_hh      = (const float*)d_in[15];
    const float* bih       = (const float*)d_in[16];
    const float* bhh       = (const float*)d_in[17];
    const float* Wh        = (const float*)d_in[18];
    const float* lng       = (const float*)d_in[19];
    const float* lnb       = (const float*)d_in[20];
    float* out = (float*)d_out;

    float *p_agg;
    __half *p_ns16, *p_node_hh, *p_ent_proj, *p_A16, *p_E16, *p_Whh16, *p_Wih16;
    cudaGetSymbolAddress((void**)&p_ns16,     g_ns16);
    cudaGetSymbolAddress((void**)&p_node_hh,  g_node_hh);
    cudaGetSymbolAddress((void**)&p_ent_proj, g_ent_proj);
    cudaGetSymbolAddress((void**)&p_agg,      g_agg);
    cudaGetSymbolAddress((void**)&p_A16,   g_A16);
    cudaGetSymbolAddress((void**)&p_E16,   g_E16);
    cudaGetSymbolAddress((void**)&p_Whh16, g_Whh16);
    cudaGetSymbolAddress((void**)&p_Wih16, g_Wih16);
    __nv_bfloat16 *pA_hi, *pA_lo, *pWs_hi, *pWs_lo;
    cudaGetSymbolAddress((void**)&pA_hi,   g_A_hi);   cudaGetSymbolAddress((void**)&pA_lo,   g_A_lo);
    cudaGetSymbolAddress((void**)&pWs_hi,  g_Ws_hi);  cudaGetSymbolAddress((void**)&pWs_lo,  g_Ws_lo);

    cudaFuncSetAttribute(k_hmma_split, cudaFuncAttributeMaxDynamicSharedMemorySize, HM_SMEM);
    cudaFuncSetAttribute(k_hmma16_nt<3>, cudaFuncAttributeMaxDynamicSharedMemorySize, HM16_SMEM);

    k_init<<<(NNEW * H_DIM + 255) / 256, 256>>>();
    k_rel<<<NREL, G3H>>>(rel_table, Wr, Wqr, W_ih);
    k_cvt<<<(NOLD * 32 + 255) / 256, 256>>>(node_emb, H_DIM, H_DIM, pA_hi, pA_lo, NOLD);
    k_cvt<<<(128 * 32 + 255) / 256, 256>>>(Ws, H_DIM, H_DIM, pWs_hi, pWs_lo, 128);
    {
        int grid = (NOLD + 127) / 128;
        k_hmma_split<<<grid, 256, HM_SMEM>>>(pA_hi, pA_lo, pWs_hi, pWs_lo, p_ns16, NOLD);
    }
    // pass A: exp(logit) + denom, single edge pass (no segmax)
    k_logit<<<E_EDGES / 8, 256>>>(head, rel, qidx, tail, bqr, Wa, ba);
    // remaining conversions + gate GEMMs (independent of logit)
    k_cvt16<<<(NOLD * 32 + 255) / 256, 256>>>(node_emb, H_DIM, H_DIM, p_A16, NOLD);
    k_cvt16<<<(NENT * 32 + 255) / 256, 256>>>(ent_table, D_EMB, D_EMB, p_E16, NENT);
    k_cvt16<<<(G3H * 32 + 255) / 256, 256>>>(W_hh, H_DIM, H_DIM,     p_Whh16, G3H);
    k_cvt16<<<(G3H * 32 + 255) / 256, 256>>>(W_ih, D_EMB, 2 * D_EMB, p_Wih16, G3H);
    {
        int grid = (NOLD + 127) / 128;
        k_hmma16_nt<3><<<grid, 256, HM16_SMEM>>>(p_A16, p_Whh16, p_node_hh, NOLD);
        int gride = (NENT + 127) / 128;
        k_hmma16_nt<3><<<gride, 256, HM16_SMEM>>>(p_E16, p_Wih16, p_ent_proj, NENT);
    }
    // pass C: gates + weighted scatter
    k_msg<<<E_EDGES / 8, 256>>>(head, rel, ent, tail, bih, bhh);
    // fused output GEMM + relu + LayerNorm
    k_out<<<(NNEW + 127) / 128, 256>>>(p_agg, Wh, lng, lnb, out, NNEW);
}

// round 13
// speedup vs baseline: 1.4154x; 1.1871x over previous
#include <cuda_runtime.h>
#include <cuda_bf16.h>
#include <cuda_fp16.h>
#include <cstdint>
#include <math.h>

#define E_EDGES 500000
#define NOLD    100000
#define NNEW    100000
#define NENT    100000
#define NREL    500
#define D_EMB   100
#define H_DIM   128
#define G3H     384

// ---------------- scratch (device globals; no allocation allowed) ----------------
__device__ __align__(16) __half   g_ns16[NOLD * H_DIM];        // node_emb @ Ws^T (fp16)
__device__ __align__(16) __half   g_node_hh[NOLD * G3H];       // node_emb @ W_hh^T (fp16)
__device__ __align__(16) __half   g_ent_proj[NENT * G3H];      // ent_table @ W_ih[:, :100]^T (fp16)
__device__ __align__(16) float    g_rel_wr[NREL * H_DIM];
__device__ __align__(16) float    g_rel_wqr[NREL * H_DIM];
__device__ __align__(16) float    g_rel_gru[NREL * G3H];
__device__ float                  g_ex[E_EDGES];
__device__ float                  g_denom[NNEW];
__device__ __align__(16) float    g_agg[NNEW * H_DIM];
__device__ __align__(16) __half   g_agg16[NNEW * H_DIM];       // agg fp16 plane for out-GEMM
// bf16 split planes (logit path only)
__device__ __align__(16) __nv_bfloat16 g_A_hi[NOLD * 128];
__device__ __align__(16) __nv_bfloat16 g_A_lo[NOLD * 128];
__device__ __align__(16) __nv_bfloat16 g_Ws_hi[128 * 128];
__device__ __align__(16) __nv_bfloat16 g_Ws_lo[128 * 128];
// fp16 planes (gate path + out path, zero-padded to K=128)
__device__ __align__(16) __half g_A16[NOLD * 128];     // node_emb fp16 (also hs gather source)
__device__ __align__(16) __half g_E16[NENT * 128];     // ent_table fp16
__device__ __align__(16) __half g_Whh16[G3H * 128];
__device__ __align__(16) __half g_Wih16[G3H * 128];
__device__ __align__(16) __half g_Wh16[128 * 128];

// ---------------- helpers ----------------
__device__ __forceinline__ uint32_t smem_u32(const void* p) {
    uint32_t a;
    asm("{ .reg .u64 t; cvta.to.shared.u64 t, %1; cvt.u32.u64 %0, t; }" : "=r"(a) : "l"(p));
    return a;
}
__device__ __forceinline__ void ldm_x4(uint32_t* r, uint32_t addr) {
    asm volatile("ldmatrix.sync.aligned.m8n8.x4.shared.b16 {%0,%1,%2,%3}, [%4];"
                 : "=r"(r[0]), "=r"(r[1]), "=r"(r[2]), "=r"(r[3]) : "r"(addr));
}
__device__ __forceinline__ void mma_bf16(float* d, const uint32_t* a, uint32_t b0, uint32_t b1) {
    asm volatile(
        "mma.sync.aligned.m16n8k16.row.col.f32.bf16.bf16.f32 "
        "{%0,%1,%2,%3}, {%4,%5,%6,%7}, {%8,%9}, {%0,%1,%2,%3};"
        : "+f"(d[0]), "+f"(d[1]), "+f"(d[2]), "+f"(d[3])
        : "r"(a[0]), "r"(a[1]), "r"(a[2]), "r"(a[3]), "r"(b0), "r"(b1));
}
__device__ __forceinline__ void mma_f16(float* d, const uint32_t* a, uint32_t b0, uint32_t b1) {
    asm volatile(
        "mma.sync.aligned.m16n8k16.row.col.f32.f16.f16.f32 "
        "{%0,%1,%2,%3}, {%4,%5,%6,%7}, {%8,%9}, {%0,%1,%2,%3};"
        : "+f"(d[0]), "+f"(d[1]), "+f"(d[2]), "+f"(d[3])
        : "r"(a[0]), "r"(a[1]), "r"(a[2]), "r"(a[3]), "r"(b0), "r"(b1));
}
__device__ __forceinline__ uint32_t swz(int r, int u) {
    return (uint32_t)(r * 256) + ((uint32_t)((u & 8) | ((u & 7) ^ (r & 7))) << 4);
}
__device__ __forceinline__ float4 ld_half4(const __half* p) {
    uint2 u = *reinterpret_cast<const uint2*>(p);
    __half2 h01 = *reinterpret_cast<__half2*>(&u.x);
    __half2 h23 = *reinterpret_cast<__half2*>(&u.y);
    float2 f01 = __half22float2(h01);
    float2 f23 = __half22float2(h23);
    return make_float4(f01.x, f01.y, f23.x, f23.y);
}

// ---------------- cvt: fp32 -> bf16 hi/lo planes [M x 128] ----------------
__global__ void k_cvt(const float* __restrict__ src, int Ksrc, int srcStride,
                      __nv_bfloat16* __restrict__ hi, __nv_bfloat16* __restrict__ lo, int M) {
    int idx = blockIdx.x * blockDim.x + threadIdx.x;
    if (idx >= M * 32) return;
    int r = idx >> 5, g = idx & 31;
    int c = g * 4;
    float4 v = make_float4(0.f, 0.f, 0.f, 0.f);
    if (c + 3 < Ksrc) v = *reinterpret_cast<const float4*>(src + (size_t)r * srcStride + c);
    __nv_bfloat16 h0 = __float2bfloat16(v.x), h1 = __float2bfloat16(v.y);
    __nv_bfloat16 h2 = __float2bfloat16(v.z), h3 = __float2bfloat16(v.w);
    __nv_bfloat16 l0 = __float2bfloat16(v.x - __bfloat162float(h0));
    __nv_bfloat16 l1 = __float2bfloat16(v.y - __bfloat162float(h1));
    __nv_bfloat16 l2 = __float2bfloat16(v.z - __bfloat162float(h2));
    __nv_bfloat16 l3 = __float2bfloat16(v.w - __bfloat162float(h3));
    uint2 hv, lv;
    hv.x = ((uint32_t)__bfloat16_as_ushort(h1) << 16) | __bfloat16_as_ushort(h0);
    hv.y = ((uint32_t)__bfloat16_as_ushort(h3) << 16) | __bfloat16_as_ushort(h2);
    lv.x = ((uint32_t)__bfloat16_as_ushort(l1) << 16) | __bfloat16_as_ushort(l0);
    lv.y = ((uint32_t)__bfloat16_as_ushort(l3) << 16) | __bfloat16_as_ushort(l2);
    *reinterpret_cast<uint2*>(hi + (size_t)r * 128 + c) = hv;
    *reinterpret_cast<uint2*>(lo + (size_t)r * 128 + c) = lv;
}

// ---------------- cvt16: fp32 -> fp16 plane [M x 128] zero-padded ----------------
__global__ void k_cvt16(const float* __restrict__ src, int Ksrc, int srcStride,
                        __half* __restrict__ dst, int M) {
    int idx = blockIdx.x * blockDim.x + threadIdx.x;
    if (idx >= M * 32) return;
    int r = idx >> 5, g = idx & 31;
    int c = g * 4;
    float4 v = make_float4(0.f, 0.f, 0.f, 0.f);
    if (c + 3 < Ksrc) v = *reinterpret_cast<const float4*>(src + (size_t)r * srcStride + c);
    __half2 h01 = __floats2half2_rn(v.x, v.y);
    __half2 h23 = __floats2half2_rn(v.z, v.w);
    uint2 o;
    o.x = *reinterpret_cast<uint32_t*>(&h01);
    o.y = *reinterpret_cast<uint32_t*>(&h23);
    *reinterpret_cast<uint2*>(dst + (size_t)r * 128 + c) = o;
}

// ---------------- bf16-split HMMA GEMM (logit path): node_s16 = A @ Ws^T, fp16 out ----------------
#define SA_HI 0
#define SA_LO 32768
#define SB_HI 65536
#define SB_LO 98304
#define HM_SMEM 131072

__global__ __launch_bounds__(256) void k_hmma_split(
    const __nv_bfloat16* __restrict__ Ahi, const __nv_bfloat16* __restrict__ Alo,
    const __nv_bfloat16* __restrict__ Bhi, const __nv_bfloat16* __restrict__ Blo,
    __half* __restrict__ C, int M) {
    extern __shared__ char smem[];
    const uint32_t sb = smem_u32(smem);
    const int tid  = threadIdx.x;
    const int lane = tid & 31;
    const int wid  = tid >> 5;
    const int warpM = wid & 3;
    const int warpN = wid >> 2;
    const int rowBase = blockIdx.x * 128;

    {
        int r = tid >> 4, g = tid & 15;
        #pragma unroll
        for (int i = 0; i < 8; i++) {
            int rr = r + i * 16;
            uint32_t soff = swz(rr, g);
            int ga = rowBase + rr;  if (ga > M - 1) ga = M - 1;
            *reinterpret_cast<uint4*>(smem + SA_HI + soff) =
                *reinterpret_cast<const uint4*>(Ahi + (size_t)ga * 128 + g * 8);
            *reinterpret_cast<uint4*>(smem + SA_LO + soff) =
                *reinterpret_cast<const uint4*>(Alo + (size_t)ga * 128 + g * 8);
            *reinterpret_cast<uint4*>(smem + SB_HI + soff) =
                *reinterpret_cast<const uint4*>(Bhi + (size_t)rr * 128 + g * 8);
            *reinterpret_cast<uint4*>(smem + SB_LO + soff) =
                *reinterpret_cast<const uint4*>(Blo + (size_t)rr * 128 + g * 8);
        }
    }
    __syncthreads();

    float acc[2][8][4];
    #pragma unroll
    for (int i = 0; i < 2; i++)
        #pragma unroll
        for (int j = 0; j < 8; j++)
            #pragma unroll
            for (int q = 0; q < 4; q++) acc[i][j][q] = 0.f;

    #pragma unroll
    for (int ks = 0; ks < 8; ks++) {
        uint32_t a_hi[2][4], a_lo[2][4];
        #pragma unroll
        for (int mi = 0; mi < 2; mi++) {
            int row  = warpM * 32 + mi * 16 + (lane & 15);
            int unit = 2 * ks + (lane >> 4);
            ldm_x4(a_hi[mi], sb + SA_HI + swz(row, unit));
            ldm_x4(a_lo[mi], sb + SA_LO + swz(row, unit));
        }
        #pragma unroll
        for (int nbp = 0; nbp < 4; nbp++) {
            int nrow = warpN * 64 + nbp * 16 + (lane & 7) + ((lane >> 4) << 3);
            int unit = 2 * ks + ((lane >> 3) & 1);
            uint32_t b_hi[4], b_lo[4];
            ldm_x4(b_hi, sb + SB_HI + swz(nrow, unit));
            ldm_x4(b_lo, sb + SB_LO + swz(nrow, unit));
            #pragma unroll
            for (int mi = 0; mi < 2; mi++) {
                #pragma unroll
                for (int na = 0; na < 2; na++) {
                    float* d = acc[mi][nbp * 2 + na];
                    mma_bf16(d, a_hi[mi], b_hi[na * 2], b_hi[na * 2 + 1]);
                    mma_bf16(d, a_hi[mi], b_lo[na * 2], b_lo[na * 2 + 1]);
                    mma_bf16(d, a_lo[mi], b_hi[na * 2], b_hi[na * 2 + 1]);
                }
            }
        }
    }

    #pragma unroll
    for (int mi = 0; mi < 2; mi++) {
        int r0 = rowBase + warpM * 32 + mi * 16 + (lane >> 2);
        #pragma unroll
        for (int nb = 0; nb < 8; nb++) {
            int col = warpN * 64 + nb * 8 + (lane & 3) * 2;
            if (r0 < M)
                *reinterpret_cast<__half2*>(C + (size_t)r0 * 128 + col) =
                    __floats2half2_rn(acc[mi][nb][0], acc[mi][nb][1]);
            if (r0 + 8 < M)
                *reinterpret_cast<__half2*>(C + (size_t)(r0 + 8) * 128 + col) =
                    __floats2half2_rn(acc[mi][nb][2], acc[mi][nb][3]);
        }
    }
}

// ---------------- fp16 single-MMA GEMM (gate path), A-resident multi-N ----------------
#define S16_A 0
#define S16_B 32768
#define HM16_SMEM 65536

template <int NT>
__global__ __launch_bounds__(256) void k_hmma16_nt(
    const __half* __restrict__ A16, const __half* __restrict__ B16,
    __half* __restrict__ C, int M) {
    extern __shared__ char smem[];
    const uint32_t sb = smem_u32(smem);
    const int tid  = threadIdx.x;
    const int lane = tid & 31;
    const int wid  = tid >> 5;
    const int warpM = wid & 3;
    const int warpN = wid >> 2;
    const int rowBase = blockIdx.x * 128;
    const int N = NT * 128;

    {
        int r = tid >> 4, g = tid & 15;
        #pragma unroll
        for (int i = 0; i < 8; i++) {
            int rr = r + i * 16;
            int ga = rowBase + rr;  if (ga > M - 1) ga = M - 1;
            *reinterpret_cast<uint4*>(smem + S16_A + swz(rr, g)) =
                *reinterpret_cast<const uint4*>(A16 + (size_t)ga * 128 + g * 8);
        }
    }

    #pragma unroll
    for (int nt = 0; nt < NT; nt++) {
        {
            int r = tid >> 4, g = tid & 15;
            #pragma unroll
            for (int i = 0; i < 8; i++) {
                int rr = r + i * 16;
                *reinterpret_cast<uint4*>(smem + S16_B + swz(rr, g)) =
                    *reinterpret_cast<const uint4*>(B16 + (size_t)(nt * 128 + rr) * 128 + g * 8);
            }
        }
        __syncthreads();

        float acc[2][8][4];
        #pragma unroll
        for (int i = 0; i < 2; i++)
            #pragma unroll
            for (int j = 0; j < 8; j++)
                #pragma unroll
                for (int q = 0; q < 4; q++) acc[i][j][q] = 0.f;

        #pragma unroll
        for (int ks = 0; ks < 8; ks++) {
            uint32_t a[2][4];
            #pragma unroll
            for (int mi = 0; mi < 2; mi++) {
                int row  = warpM * 32 + mi * 16 + (lane & 15);
                int unit = 2 * ks + (lane >> 4);
                ldm_x4(a[mi], sb + S16_A + swz(row, unit));
            }
            #pragma unroll
            for (int nbp = 0; nbp < 4; nbp++) {
                int nrow = warpN * 64 + nbp * 16 + (lane & 7) + ((lane >> 4) << 3);
                int unit = 2 * ks + ((lane >> 3) & 1);
                uint32_t b[4];
                ldm_x4(b, sb + S16_B + swz(nrow, unit));
                #pragma unroll
                for (int mi = 0; mi < 2; mi++) {
                    #pragma unroll
                    for (int na = 0; na < 2; na++)
                        mma_f16(acc[mi][nbp * 2 + na], a[mi], b[na * 2], b[na * 2 + 1]);
                }
            }
        }

        #pragma unroll
        for (int mi = 0; mi < 2; mi++) {
            int r0 = rowBase + warpM * 32 + mi * 16 + (lane >> 2);
            #pragma unroll
            for (int nb = 0; nb < 8; nb++) {
                int col = nt * 128 + warpN * 64 + nb * 8 + (lane & 3) * 2;
                if (r0 < M)
                    *reinterpret_cast<__half2*>(C + (size_t)r0 * N + col) =
                        __floats2half2_rn(acc[mi][nb][0], acc[mi][nb][1]);
                if (r0 + 8 < M)
                    *reinterpret_cast<__half2*>(C + (size_t)(r0 + 8) * N + col) =
                        __floats2half2_rn(acc[mi][nb][2], acc[mi][nb][3]);
            }
        }
        __syncthreads();
    }
}

// ---------------- out GEMM on fp16 HMMA + relu + LayerNorm (same load path as k_hmma16_nt) ----------------
__global__ __launch_bounds__(256) void k_out16(
    const __half* __restrict__ A16,   // agg16 [M x 128]
    const __half* __restrict__ B16,   // Wh16 [128 x 128]
    const float* __restrict__ lng, const float* __restrict__ lnb,
    float* __restrict__ C, int M) {
    extern __shared__ char smem[];
    const uint32_t sb = smem_u32(smem);
    const int tid  = threadIdx.x;
    const int lane = tid & 31;
    const int wid  = tid >> 5;
    const int warpM = wid & 3;
    const int warpN = wid >> 2;
    const int rowBase = blockIdx.x * 128;

    {
        int r = tid >> 4, g = tid & 15;
        #pragma unroll
        for (int i = 0; i < 8; i++) {
            int rr = r + i * 16;
            int ga = rowBase + rr;  if (ga > M - 1) ga = M - 1;
            *reinterpret_cast<uint4*>(smem + S16_A + swz(rr, g)) =
                *reinterpret_cast<const uint4*>(A16 + (size_t)ga * 128 + g * 8);
            *reinterpret_cast<uint4*>(smem + S16_B + swz(rr, g)) =
                *reinterpret_cast<const uint4*>(B16 + (size_t)rr * 128 + g * 8);
        }
    }
    __syncthreads();

    float acc[2][8][4];
    #pragma unroll
    for (int i = 0; i < 2; i++)
        #pragma unroll
        for (int j = 0; j < 8; j++)
            #pragma unroll
            for (int q = 0; q < 4; q++) acc[i][j][q] = 0.f;

    #pragma unroll
    for (int ks = 0; ks < 8; ks++) {
        uint32_t a[2][4];
        #pragma unroll
        for (int mi = 0; mi < 2; mi++) {
            int row  = warpM * 32 + mi * 16 + (lane & 15);
            int unit = 2 * ks + (lane >> 4);
            ldm_x4(a[mi], sb + S16_A + swz(row, unit));
        }
        #pragma unroll
        for (int nbp = 0; nbp < 4; nbp++) {
            int nrow = warpN * 64 + nbp * 16 + (lane & 7) + ((lane >> 4) << 3);
            int unit = 2 * ks + ((lane >> 3) & 1);
            uint32_t b[4];
            ldm_x4(b, sb + S16_B + swz(nrow, unit));
            #pragma unroll
            for (int mi = 0; mi < 2; mi++) {
                #pragma unroll
                for (int na = 0; na < 2; na++)
                    mma_f16(acc[mi][nbp * 2 + na], a[mi], b[na * 2], b[na * 2 + 1]);
            }
        }
    }
    __syncthreads();   // all smem tile reads done; reuse for LN stats

    float* s_sum = reinterpret_cast<float*>(smem);          // [128][2]
    float* s_sq  = reinterpret_cast<float*>(smem + 1024);   // [128][2]

    #pragma unroll
    for (int mi = 0; mi < 2; mi++) {
        #pragma unroll
        for (int half = 0; half < 2; half++) {
            float sum = 0.f, sq = 0.f;
            #pragma unroll
            for (int nb = 0; nb < 8; nb++) {
                float v0 = fmaxf(acc[mi][nb][half * 2], 0.f);
                float v1 = fmaxf(acc[mi][nb][half * 2 + 1], 0.f);
                acc[mi][nb][half * 2]     = v0;
                acc[mi][nb][half * 2 + 1] = v1;
                sum += v0 + v1;
                sq  += v0 * v0 + v1 * v1;
            }
            sum += __shfl_xor_sync(0xffffffffu, sum, 1);
            sq  += __shfl_xor_sync(0xffffffffu, sq, 1);
            sum += __shfl_xor_sync(0xffffffffu, sum, 2);
            sq  += __shfl_xor_sync(0xffffffffu, sq, 2);
            if ((lane & 3) == 0) {
                int r = warpM * 32 + mi * 16 + half * 8 + (lane >> 2);
                s_sum[r * 2 + warpN] = sum;
                s_sq [r * 2 + warpN] = sq;
            }
        }
    }
    __syncthreads();

    #pragma unroll
    for (int mi = 0; mi < 2; mi++) {
        #pragma unroll
        for (int half = 0; half < 2; half++) {
            int r = warpM * 32 + mi * 16 + half * 8 + (lane >> 2);
            float sum = s_sum[r * 2] + s_sum[r * 2 + 1];
            float sq  = s_sq [r * 2] + s_sq [r * 2 + 1];
            float mean = sum * (1.f / 128.f);
            float var  = sq * (1.f / 128.f) - mean * mean;
            float inv  = rsqrtf(var + 1e-5f);
            int gr = rowBase + r;
            if (gr < M) {
                #pragma unroll
                for (int nb = 0; nb < 8; nb++) {
                    int col = warpN * 64 + nb * 8 + (lane & 3) * 2;
                    float o0 = lng[col]     * (acc[mi][nb][half * 2]     - mean) * inv + lnb[col];
                    float o1 = lng[col + 1] * (acc[mi][nb][half * 2 + 1] - mean) * inv + lnb[col + 1];
                    *reinterpret_cast<float2*>(C + (size_t)gr * 128 + col) = make_float2(o0, o1);
                }
            }
        }
    }
}

// ---------------- small helpers ----------------
__device__ __forceinline__ float4 f4add(float4 a, float4 b) {
    return make_float4(a.x + b.x, a.y + b.y, a.z + b.z, a.w + b.w);
}
__device__ __forceinline__ float4 f4add3(float4 a, float4 b, float4 c) {
    return make_float4(a.x + b.x + c.x, a.y + b.y + c.y, a.z + b.z + c.z, a.w + b.w + c.w);
}
__device__ __forceinline__ float sigf(float x) { return 1.f / (1.f + expf(-x)); }
__device__ __forceinline__ float4 sig4(float4 a) {
    return make_float4(sigf(a.x), sigf(a.y), sigf(a.z), sigf(a.w));
}

// ---------------- init (zero scratch) ----------------
__global__ void k_init() {
    int i = blockIdx.x * blockDim.x + threadIdx.x;
    if (i < NNEW * H_DIM) g_agg[i] = 0.f;
    if (i < NNEW) g_denom[i] = 0.f;
}

// ---------------- relation-table projections (tiny, fp32) ----------------
__global__ void k_rel(const float* __restrict__ rel_table,
                      const float* __restrict__ Wr,
                      const float* __restrict__ Wqr,
                      const float* __restrict__ W_ih) {
    __shared__ float sh[D_EMB];
    int r = blockIdx.x;
    int j = threadIdx.x;  // 384 threads
    if (j < D_EMB) sh[j] = rel_table[r * D_EMB + j];
    __syncthreads();
    float s = 0.f;
    const float* wrow = W_ih + j * (2 * D_EMB) + D_EMB;
    #pragma unroll 4
    for (int d = 0; d < D_EMB; d++) s = fmaf(sh[d], wrow[d], s);
    g_rel_gru[r * G3H + j] = s;
    if (j < H_DIM) {
        float s1 = 0.f, s2 = 0.f;
        #pragma unroll 4
        for (int d = 0; d < D_EMB; d++) {
            s1 = fmaf(sh[d], Wr[j * D_EMB + d], s1);
            s2 = fmaf(sh[d], Wqr[j * D_EMB + d], s2);
        }
        g_rel_wr[r * H_DIM + j] = s1;
        g_rel_wqr[r * H_DIM + j] = s2;
    }
}

// ---------------- pass A: exp(logit) + denom (softmax shift-invariance: no segmax pass) ----------------
__global__ __launch_bounds__(256) void k_logit(
    const int* __restrict__ head, const int* __restrict__ rel,
    const int* __restrict__ qidx, const int* __restrict__ tail,
    const float* __restrict__ bqr, const float* __restrict__ Wa,
    const float* __restrict__ ba) {
    int e = blockIdx.x * 8 + (threadIdx.x >> 5);
    if (e >= E_EDGES) return;
    int lane = threadIdx.x & 31;
    int h = head[e], rl = rel[e], qq = qidx[e];
    const float4* rw = reinterpret_cast<const float4*>(g_rel_wr) + (size_t)rl * 32;
    const float4* qw = reinterpret_cast<const float4*>(g_rel_wqr) + (size_t)qq * 32;
    float4 a = ld_half4(g_ns16 + (size_t)h * 128 + lane * 4);
    float4 b = rw[lane];
    float4 c = qw[lane];
    float4 bq = reinterpret_cast<const float4*>(bqr)[lane];
    float4 wa = reinterpret_cast<const float4*>(Wa)[lane];
    float x0 = fmaxf(a.x + b.x + c.x + bq.x, 0.f);
    float x1 = fmaxf(a.y + b.y + c.y + bq.y, 0.f);
    float x2 = fmaxf(a.z + b.z + c.z + bq.z, 0.f);
    float x3 = fmaxf(a.w + b.w + c.w + bq.w, 0.f);
    float s = x0 * wa.x + x1 * wa.y + x2 * wa.z + x3 * wa.w;
    #pragma unroll
    for (int m = 16; m; m >>= 1) s += __shfl_xor_sync(0xffffffffu, s, m);
    if (lane == 0) {
        float ex = expf(s + ba[0]);     // logits are O(1): exp is safe without max-shift
        g_ex[e] = ex;
        atomicAdd(&g_denom[tail[e]], ex);
    }
}

// ---------------- pass C: GRU gates + weighted scatter-add (fp16 gathers) ----------------
__global__ __launch_bounds__(256) void k_msg(
    const int* __restrict__ head, const int* __restrict__ rel,
    const int* __restrict__ ent, const int* __restrict__ tail,
    const float* __restrict__ bih, const float* __restrict__ bhh) {
    int e = blockIdx.x * 8 + (threadIdx.x >> 5);
    if (e >= E_EDGES) return;
    int lane = threadIdx.x & 31;
    int hd = head[e], rl = rel[e], en = ent[e], tl = tail[e];
    const __half* ep = g_ent_proj + (size_t)en * G3H;
    const __half* nh = g_node_hh + (size_t)hd * G3H;
    const float4* rg = reinterpret_cast<const float4*>(g_rel_gru) + (size_t)rl * 96;
    const float4* bi = reinterpret_cast<const float4*>(bih);
    const float4* bh = reinterpret_cast<const float4*>(bhh);

    float4 ep_r = ld_half4(ep + lane * 4);
    float4 ep_z = ld_half4(ep + 128 + lane * 4);
    float4 ep_n = ld_half4(ep + 256 + lane * 4);
    float4 nh_r = ld_half4(nh + lane * 4);
    float4 nh_z = ld_half4(nh + 128 + lane * 4);
    float4 nh_n = ld_half4(nh + 256 + lane * 4);

    float4 gr = f4add3(ep_r, rg[lane],      bi[lane]);
    float4 hr = f4add (nh_r, bh[lane]);
    float4 gz = f4add3(ep_z, rg[lane + 32], bi[lane + 32]);
    float4 hz = f4add (nh_z, bh[lane + 32]);
    float4 gn = f4add3(ep_n, rg[lane + 64], bi[lane + 64]);
    float4 hn = f4add (nh_n, bh[lane + 64]);

    float4 r4 = sig4(f4add(gr, hr));
    float4 z4 = sig4(f4add(gz, hz));
    float4 n4;
    n4.x = tanhf(gn.x + r4.x * hn.x);
    n4.y = tanhf(gn.y + r4.y * hn.y);
    n4.z = tanhf(gn.z + r4.z * hn.z);
    n4.w = tanhf(gn.w + r4.w * hn.w);

    float4 hs = ld_half4(g_A16 + (size_t)hd * 128 + lane * 4);
    float alpha = g_ex[e] / (g_denom[tl] + 1e-6f);

    float mx = alpha * ((1.f - z4.x) * n4.x + z4.x * hs.x);
    float my = alpha * ((1.f - z4.y) * n4.y + z4.y * hs.y);
    float mz = alpha * ((1.f - z4.z) * n4.z + z4.z * hs.z);
    float mw = alpha * ((1.f - z4.w) * n4.w + z4.w * hs.w);

    float* dst = &g_agg[(size_t)tl * H_DIM + lane * 4];
    asm volatile("red.global.add.v4.f32 [%0], {%1,%2,%3,%4};"
                 :: "l"(dst), "f"(mx), "f"(my), "f"(mz), "f"(mw) : "memory");
}

// ---------------- launcher ----------------
extern "C" void kernel_launch(void* const* d_in, const int* in_sizes, int n_in,
                              void* d_out, int out_size) {
    const int*   head      = (const int*)d_in[0];
    const int*   rel       = (const int*)d_in[1];
    const int*   ent       = (const int*)d_in[2];
    const int*   tail      = (const int*)d_in[3];
    const int*   qidx      = (const int*)d_in[4];
    const float* node_emb  = (const float*)d_in[5];
    const float* ent_table = (const float*)d_in[6];
    const float* rel_table = (const float*)d_in[7];
    const float* Ws        = (const float*)d_in[8];
    const float* Wr        = (const float*)d_in[9];
    const float* Wqr       = (const float*)d_in[10];
    const float* bqr       = (const float*)d_in[11];
    const float* Wa        = (const float*)d_in[12];
    const float* ba        = (const float*)d_in[13];
    const float* W_ih      = (const float*)d_in[14];
    const float* W_hh      = (const float*)d_in[15];
    const float* bih       = (const float*)d_in[16];
    const float* bhh       = (const float*)d_in[17];
    const float* Wh        = (const float*)d_in[18];
    const float* lng       = (const float*)d_in[19];
    const float* lnb       = (const float*)d_in[20];
    float* out = (float*)d_out;

    float *p_agg;
    __half *p_ns16, *p_node_hh, *p_ent_proj, *p_A16, *p_E16, *p_Whh16, *p_Wih16, *p_Wh16, *p_agg16;
    cudaGetSymbolAddress((void**)&p_ns16,     g_ns16);
    cudaGetSymbolAddress((void**)&p_node_hh,  g_node_hh);
    cudaGetSymbolAddress((void**)&p_ent_proj, g_ent_proj);
    cudaGetSymbolAddress((void**)&p_agg,      g_agg);
    cudaGetSymbolAddress((void**)&p_agg16,    g_agg16);
    cudaGetSymbolAddress((void**)&p_A16,   g_A16);
    cudaGetSymbolAddress((void**)&p_E16,   g_E16);
    cudaGetSymbolAddress((void**)&p_Whh16, g_Whh16);
    cudaGetSymbolAddress((void**)&p_Wih16, g_Wih16);
    cudaGetSymbolAddress((void**)&p_Wh16,  g_Wh16);
    __nv_bfloat16 *pA_hi, *pA_lo, *pWs_hi, *pWs_lo;
    cudaGetSymbolAddress((void**)&pA_hi,   g_A_hi);   cudaGetSymbolAddress((void**)&pA_lo,   g_A_lo);
    cudaGetSymbolAddress((void**)&pWs_hi,  g_Ws_hi);  cudaGetSymbolAddress((void**)&pWs_lo,  g_Ws_lo);

    cudaFuncSetAttribute(k_hmma_split, cudaFuncAttributeMaxDynamicSharedMemorySize, HM_SMEM);
    cudaFuncSetAttribute(k_hmma16_nt<3>, cudaFuncAttributeMaxDynamicSharedMemorySize, HM16_SMEM);
    cudaFuncSetAttribute(k_out16, cudaFuncAttributeMaxDynamicSharedMemorySize, HM16_SMEM);

    k_init<<<(NNEW * H_DIM + 255) / 256, 256>>>();
    k_rel<<<NREL, G3H>>>(rel_table, Wr, Wqr, W_ih);
    k_cvt<<<(NOLD * 32 + 255) / 256, 256>>>(node_emb, H_DIM, H_DIM, pA_hi, pA_lo, NOLD);
    k_cvt<<<(128 * 32 + 255) / 256, 256>>>(Ws, H_DIM, H_DIM, pWs_hi, pWs_lo, 128);
    {
        int grid = (NOLD + 127) / 128;
        k_hmma_split<<<grid, 256, HM_SMEM>>>(pA_hi, pA_lo, pWs_hi, pWs_lo, p_ns16, NOLD);
    }
    // pass A: exp(logit) + denom, single edge pass (no segmax)
    k_logit<<<E_EDGES / 8, 256>>>(head, rel, qidx, tail, bqr, Wa, ba);
    // remaining conversions + gate GEMMs (independent of logit)
    k_cvt16<<<(NOLD * 32 + 255) / 256, 256>>>(node_emb, H_DIM, H_DIM, p_A16, NOLD);
    k_cvt16<<<(NENT * 32 + 255) / 256, 256>>>(ent_table, D_EMB, D_EMB, p_E16, NENT);
    k_cvt16<<<(G3H * 32 + 255) / 256, 256>>>(W_hh, H_DIM, H_DIM,     p_Whh16, G3H);
    k_cvt16<<<(G3H * 32 + 255) / 256, 256>>>(W_ih, D_EMB, 2 * D_EMB, p_Wih16, G3H);
    k_cvt16<<<(128 * 32 + 255) / 256, 256>>>(Wh, H_DIM, H_DIM, p_Wh16, 128);
    {
        int grid = (NOLD + 127) / 128;
        k_hmma16_nt<3><<<grid, 256, HM16_SMEM>>>(p_A16, p_Whh16, p_node_hh, NOLD);
        int gride = (NENT + 127) / 128;
        k_hmma16_nt<3><<<gride, 256, HM16_SMEM>>>(p_E16, p_Wih16, p_ent_proj, NENT);
    }
    // pass C: gates + weighted scatter
    k_msg<<<E_EDGES / 8, 256>>>(head, rel, ent, tail, bih, bhh);
    // out: agg -> fp16 plane, HMMA GEMM + relu + LayerNorm
    k_cvt16<<<(NNEW * 32 + 255) / 256, 256>>>(p_agg, H_DIM, H_DIM, p_agg16, NNEW);
    k_out16<<<(NNEW + 127) / 128, 256, HM16_SMEM>>>(p_agg16, p_Wh16, lng, lnb, out, NNEW);
}

// round 14
// speedup vs baseline: 1.5156x; 1.0708x over previous
#include <cuda_runtime.h>
#include <cuda_fp16.h>
#include <cstdint>
#include <math.h>

#define E_EDGES 500000
#define NOLD    100000
#define NNEW    100000
#define NENT    100000
#define NREL    500
#define D_EMB   100
#define H_DIM   128
#define G3H     384

// ---------------- scratch (device globals; no allocation allowed) ----------------
__device__ __align__(16) __half   g_ns16[NOLD * H_DIM];        // node_emb @ Ws^T (fp16)
__device__ __align__(16) __half   g_node_hh[NOLD * G3H];       // node_emb @ W_hh^T (fp16)
__device__ __align__(16) __half   g_ent_proj[NENT * G3H];      // ent_table @ W_ih[:, :100]^T (fp16)
__device__ __align__(16) float    g_rel_wr[NREL * H_DIM];
__device__ __align__(16) float    g_rel_wqr[NREL * H_DIM];     // includes +bqr folded in
__device__ __align__(16) float    g_rel_gru[NREL * G3H];
__device__ float                  g_ex[E_EDGES];
__device__ float                  g_denom[NNEW];
__device__ __align__(16) float    g_agg[NNEW * H_DIM];
__device__ __align__(16) __half   g_agg16[NNEW * H_DIM];
// fp16 planes (zero-padded to K=128)
__device__ __align__(16) __half g_A16[NOLD * 128];     // node_emb fp16 (GEMM A + hs gather source)
__device__ __align__(16) __half g_E16[NENT * 128];     // ent_table fp16
__device__ __align__(16) __half g_Ws16[128 * 128];
__device__ __align__(16) __half g_Whh16[G3H * 128];
__device__ __align__(16) __half g_Wih16[G3H * 128];
__device__ __align__(16) __half g_Wh16[128 * 128];

// ---------------- helpers ----------------
__device__ __forceinline__ uint32_t smem_u32(const void* p) {
    uint32_t a;
    asm("{ .reg .u64 t; cvta.to.shared.u64 t, %1; cvt.u32.u64 %0, t; }" : "=r"(a) : "l"(p));
    return a;
}
__device__ __forceinline__ void ldm_x4(uint32_t* r, uint32_t addr) {
    asm volatile("ldmatrix.sync.aligned.m8n8.x4.shared.b16 {%0,%1,%2,%3}, [%4];"
                 : "=r"(r[0]), "=r"(r[1]), "=r"(r[2]), "=r"(r[3]) : "r"(addr));
}
__device__ __forceinline__ void mma_f16(float* d, const uint32_t* a, uint32_t b0, uint32_t b1) {
    asm volatile(
        "mma.sync.aligned.m16n8k16.row.col.f32.f16.f16.f32 "
        "{%0,%1,%2,%3}, {%4,%5,%6,%7}, {%8,%9}, {%0,%1,%2,%3};"
        : "+f"(d[0]), "+f"(d[1]), "+f"(d[2]), "+f"(d[3])
        : "r"(a[0]), "r"(a[1]), "r"(a[2]), "r"(a[3]), "r"(b0), "r"(b1));
}
__device__ __forceinline__ uint32_t swz(int r, int u) {
    return (uint32_t)(r * 256) + ((uint32_t)((u & 8) | ((u & 7) ^ (r & 7))) << 4);
}
__device__ __forceinline__ float4 ld_half4(const __half* p) {
    uint2 u = *reinterpret_cast<const uint2*>(p);
    __half2 h01 = *reinterpret_cast<__half2*>(&u.x);
    __half2 h23 = *reinterpret_cast<__half2*>(&u.y);
    float2 f01 = __half22float2(h01);
    float2 f23 = __half22float2(h23);
    return make_float4(f01.x, f01.y, f23.x, f23.y);
}
__device__ __forceinline__ float tanh_fast(float x) {
    float t;
    asm("tanh.approx.f32 %0, %1;" : "=f"(t) : "f"(x));
    return t;
}
__device__ __forceinline__ float sig_fast(float x) {
    return 1.f / (1.f + __expf(-x));
}
__device__ __forceinline__ float4 sig4f(float4 a) {
    return make_float4(sig_fast(a.x), sig_fast(a.y), sig_fast(a.z), sig_fast(a.w));
}
__device__ __forceinline__ float4 f4add(float4 a, float4 b) {
    return make_float4(a.x + b.x, a.y + b.y, a.z + b.z, a.w + b.w);
}
__device__ __forceinline__ float4 f4add3(float4 a, float4 b, float4 c) {
    return make_float4(a.x + b.x + c.x, a.y + b.y + c.y, a.z + b.z + c.z, a.w + b.w + c.w);
}

// ---------------- cvt16: fp32 -> fp16 plane [M x 128] zero-padded ----------------
__global__ void k_cvt16(const float* __restrict__ src, int Ksrc, int srcStride,
                        __half* __restrict__ dst, int M) {
    int idx = blockIdx.x * blockDim.x + threadIdx.x;
    if (idx >= M * 32) return;
    int r = idx >> 5, g = idx & 31;
    int c = g * 4;
    float4 v = make_float4(0.f, 0.f, 0.f, 0.f);
    if (c + 3 < Ksrc) v = *reinterpret_cast<const float4*>(src + (size_t)r * srcStride + c);
    __half2 h01 = __floats2half2_rn(v.x, v.y);
    __half2 h23 = __floats2half2_rn(v.z, v.w);
    uint2 o;
    o.x = *reinterpret_cast<uint32_t*>(&h01);
    o.y = *reinterpret_cast<uint32_t*>(&h23);
    *reinterpret_cast<uint2*>(dst + (size_t)r * 128 + c) = o;
}

// ---------------- fp16 single-MMA GEMM, A-resident multi-N ----------------
#define S16_A 0
#define S16_B 32768
#define HM16_SMEM 65536

template <int NT>
__global__ __launch_bounds__(256) void k_hmma16_nt(
    const __half* __restrict__ A16, const __half* __restrict__ B16,
    __half* __restrict__ C, int M) {
    extern __shared__ char smem[];
    const uint32_t sb = smem_u32(smem);
    const int tid  = threadIdx.x;
    const int lane = tid & 31;
    const int wid  = tid >> 5;
    const int warpM = wid & 3;
    const int warpN = wid >> 2;
    const int rowBase = blockIdx.x * 128;
    const int N = NT * 128;

    {
        int r = tid >> 4, g = tid & 15;
        #pragma unroll
        for (int i = 0; i < 8; i++) {
            int rr = r + i * 16;
            int ga = rowBase + rr;  if (ga > M - 1) ga = M - 1;
            *reinterpret_cast<uint4*>(smem + S16_A + swz(rr, g)) =
                *reinterpret_cast<const uint4*>(A16 + (size_t)ga * 128 + g * 8);
        }
    }

    #pragma unroll
    for (int nt = 0; nt < NT; nt++) {
        {
            int r = tid >> 4, g = tid & 15;
            #pragma unroll
            for (int i = 0; i < 8; i++) {
                int rr = r + i * 16;
                *reinterpret_cast<uint4*>(smem + S16_B + swz(rr, g)) =
                    *reinterpret_cast<const uint4*>(B16 + (size_t)(nt * 128 + rr) * 128 + g * 8);
            }
        }
        __syncthreads();

        float acc[2][8][4];
        #pragma unroll
        for (int i = 0; i < 2; i++)
            #pragma unroll
            for (int j = 0; j < 8; j++)
                #pragma unroll
                for (int q = 0; q < 4; q++) acc[i][j][q] = 0.f;

        #pragma unroll
        for (int ks = 0; ks < 8; ks++) {
            uint32_t a[2][4];
            #pragma unroll
            for (int mi = 0; mi < 2; mi++) {
                int row  = warpM * 32 + mi * 16 + (lane & 15);
                int unit = 2 * ks + (lane >> 4);
                ldm_x4(a[mi], sb + S16_A + swz(row, unit));
            }
            #pragma unroll
            for (int nbp = 0; nbp < 4; nbp++) {
                int nrow = warpN * 64 + nbp * 16 + (lane & 7) + ((lane >> 4) << 3);
                int unit = 2 * ks + ((lane >> 3) & 1);
                uint32_t b[4];
                ldm_x4(b, sb + S16_B + swz(nrow, unit));
                #pragma unroll
                for (int mi = 0; mi < 2; mi++) {
                    #pragma unroll
                    for (int na = 0; na < 2; na++)
                        mma_f16(acc[mi][nbp * 2 + na], a[mi], b[na * 2], b[na * 2 + 1]);
                }
            }
        }

        #pragma unroll
        for (int mi = 0; mi < 2; mi++) {
            int r0 = rowBase + warpM * 32 + mi * 16 + (lane >> 2);
            #pragma unroll
            for (int nb = 0; nb < 8; nb++) {
                int col = nt * 128 + warpN * 64 + nb * 8 + (lane & 3) * 2;
                if (r0 < M)
                    *reinterpret_cast<__half2*>(C + (size_t)r0 * N + col) =
                        __floats2half2_rn(acc[mi][nb][0], acc[mi][nb][1]);
                if (r0 + 8 < M)
                    *reinterpret_cast<__half2*>(C + (size_t)(r0 + 8) * N + col) =
                        __floats2half2_rn(acc[mi][nb][2], acc[mi][nb][3]);
            }
        }
        __syncthreads();
    }
}

// ---------------- out GEMM on fp16 HMMA + relu + LayerNorm ----------------
__global__ __launch_bounds__(256) void k_out16(
    const __half* __restrict__ A16,   // agg16 [M x 128]
    const __half* __restrict__ B16,   // Wh16 [128 x 128]
    const float* __restrict__ lng, const float* __restrict__ lnb,
    float* __restrict__ C, int M) {
    extern __shared__ char smem[];
    const uint32_t sb = smem_u32(smem);
    const int tid  = threadIdx.x;
    const int lane = tid & 31;
    const int wid  = tid >> 5;
    const int warpM = wid & 3;
    const int warpN = wid >> 2;
    const int rowBase = blockIdx.x * 128;

    {
        int r = tid >> 4, g = tid & 15;
        #pragma unroll
        for (int i = 0; i < 8; i++) {
            int rr = r + i * 16;
            int ga = rowBase + rr;  if (ga > M - 1) ga = M - 1;
            *reinterpret_cast<uint4*>(smem + S16_A + swz(rr, g)) =
                *reinterpret_cast<const uint4*>(A16 + (size_t)ga * 128 + g * 8);
            *reinterpret_cast<uint4*>(smem + S16_B + swz(rr, g)) =
                *reinterpret_cast<const uint4*>(B16 + (size_t)rr * 128 + g * 8);
        }
    }
    __syncthreads();

    float acc[2][8][4];
    #pragma unroll
    for (int i = 0; i < 2; i++)
        #pragma unroll
        for (int j = 0; j < 8; j++)
            #pragma unroll
            for (int q = 0; q < 4; q++) acc[i][j][q] = 0.f;

    #pragma unroll
    for (int ks = 0; ks < 8; ks++) {
        uint32_t a[2][4];
        #pragma unroll
        for (int mi = 0; mi < 2; mi++) {
            int row  = warpM * 32 + mi * 16 + (lane & 15);
            int unit = 2 * ks + (lane >> 4);
            ldm_x4(a[mi], sb + S16_A + swz(row, unit));
        }
        #pragma unroll
        for (int nbp = 0; nbp < 4; nbp++) {
            int nrow = warpN * 64 + nbp * 16 + (lane & 7) + ((lane >> 4) << 3);
            int unit = 2 * ks + ((lane >> 3) & 1);
            uint32_t b[4];
            ldm_x4(b, sb + S16_B + swz(nrow, unit));
            #pragma unroll
            for (int mi = 0; mi < 2; mi++) {
                #pragma unroll
                for (int na = 0; na < 2; na++)
                    mma_f16(acc[mi][nbp * 2 + na], a[mi], b[na * 2], b[na * 2 + 1]);
            }
        }
    }
    __syncthreads();   // all smem tile reads done; reuse for LN stats

    float* s_sum = reinterpret_cast<float*>(smem);          // [128][2]
    float* s_sq  = reinterpret_cast<float*>(smem + 1024);   // [128][2]

    #pragma unroll
    for (int mi = 0; mi < 2; mi++) {
        #pragma unroll
        for (int half = 0; half < 2; half++) {
            float sum = 0.f, sq = 0.f;
            #pragma unroll
            for (int nb = 0; nb < 8; nb++) {
                float v0 = fmaxf(acc[mi][nb][half * 2], 0.f);
                float v1 = fmaxf(acc[mi][nb][half * 2 + 1], 0.f);
                acc[mi][nb][half * 2]     = v0;
                acc[mi][nb][half * 2 + 1] = v1;
                sum += v0 + v1;
                sq  += v0 * v0 + v1 * v1;
            }
            sum += __shfl_xor_sync(0xffffffffu, sum, 1);
            sq  += __shfl_xor_sync(0xffffffffu, sq, 1);
            sum += __shfl_xor_sync(0xffffffffu, sum, 2);
            sq  += __shfl_xor_sync(0xffffffffu, sq, 2);
            if ((lane & 3) == 0) {
                int r = warpM * 32 + mi * 16 + half * 8 + (lane >> 2);
                s_sum[r * 2 + warpN] = sum;
                s_sq [r * 2 + warpN] = sq;
            }
        }
    }
    __syncthreads();

    #pragma unroll
    for (int mi = 0; mi < 2; mi++) {
        #pragma unroll
        for (int half = 0; half < 2; half++) {
            int r = warpM * 32 + mi * 16 + half * 8 + (lane >> 2);
            float sum = s_sum[r * 2] + s_sum[r * 2 + 1];
            float sq  = s_sq [r * 2] + s_sq [r * 2 + 1];
            float mean = sum * (1.f / 128.f);
            float var  = sq * (1.f / 128.f) - mean * mean;
            float inv  = rsqrtf(var + 1e-5f);
            int gr = rowBase + r;
            if (gr < M) {
                #pragma unroll
                for (int nb = 0; nb < 8; nb++) {
                    int col = warpN * 64 + nb * 8 + (lane & 3) * 2;
                    float o0 = lng[col]     * (acc[mi][nb][half * 2]     - mean) * inv + lnb[col];
                    float o1 = lng[col + 1] * (acc[mi][nb][half * 2 + 1] - mean) * inv + lnb[col + 1];
                    *reinterpret_cast<float2*>(C + (size_t)gr * 128 + col) = make_float2(o0, o1);
                }
            }
        }
    }
}

// ---------------- init (zero scratch) ----------------
__global__ void k_init() {
    int i = blockIdx.x * blockDim.x + threadIdx.x;
    if (i < NNEW * H_DIM) g_agg[i] = 0.f;
    if (i < NNEW) g_denom[i] = 0.f;
}

// ---------------- relation-table projections (tiny, fp32; bqr folded into wqr) ----------------
__global__ void k_rel(const float* __restrict__ rel_table,
                      const float* __restrict__ Wr,
                      const float* __restrict__ Wqr,
                      const float* __restrict__ W_ih,
                      const float* __restrict__ bqr) {
    __shared__ float sh[D_EMB];
    int r = blockIdx.x;
    int j = threadIdx.x;  // 384 threads
    if (j < D_EMB) sh[j] = rel_table[r * D_EMB + j];
    __syncthreads();
    float s = 0.f;
    const float* wrow = W_ih + j * (2 * D_EMB) + D_EMB;
    #pragma unroll 4
    for (int d = 0; d < D_EMB; d++) s = fmaf(sh[d], wrow[d], s);
    g_rel_gru[r * G3H + j] = s;
    if (j < H_DIM) {
        float s1 = 0.f, s2 = 0.f;
        #pragma unroll 4
        for (int d = 0; d < D_EMB; d++) {
            s1 = fmaf(sh[d], Wr[j * D_EMB + d], s1);
            s2 = fmaf(sh[d], Wqr[j * D_EMB + d], s2);
        }
        g_rel_wr[r * H_DIM + j] = s1;
        g_rel_wqr[r * H_DIM + j] = s2 + bqr[j];
    }
}

// ---------------- pass A: exp(logit) + denom ----------------
__global__ __launch_bounds__(256) void k_logit(
    const int* __restrict__ head, const int* __restrict__ rel,
    const int* __restrict__ qidx, const int* __restrict__ tail,
    const float* __restrict__ Wa, const float* __restrict__ ba) {
    int e = blockIdx.x * 8 + (threadIdx.x >> 5);
    if (e >= E_EDGES) return;
    int lane = threadIdx.x & 31;
    int h = head[e], rl = rel[e], qq = qidx[e];
    const float4* rw = reinterpret_cast<const float4*>(g_rel_wr) + (size_t)rl * 32;
    const float4* qw = reinterpret_cast<const float4*>(g_rel_wqr) + (size_t)qq * 32;
    float4 a = ld_half4(g_ns16 + (size_t)h * 128 + lane * 4);
    float4 b = rw[lane];
    float4 c = qw[lane];
    float4 wa = reinterpret_cast<const float4*>(Wa)[lane];
    float x0 = fmaxf(a.x + b.x + c.x, 0.f);
    float x1 = fmaxf(a.y + b.y + c.y, 0.f);
    float x2 = fmaxf(a.z + b.z + c.z, 0.f);
    float x3 = fmaxf(a.w + b.w + c.w, 0.f);
    float s = x0 * wa.x + x1 * wa.y + x2 * wa.z + x3 * wa.w;
    #pragma unroll
    for (int m = 16; m; m >>= 1) s += __shfl_xor_sync(0xffffffffu, s, m);
    if (lane == 0) {
        float ex = __expf(s + ba[0]);   // logits are O(1): exp safe without max-shift
        g_ex[e] = ex;
        atomicAdd(&g_denom[tail[e]], ex);
    }
}

// ---------------- pass C: GRU gates + weighted scatter-add ----------------
__global__ __launch_bounds__(256) void k_msg(
    const int* __restrict__ head, const int* __restrict__ rel,
    const int* __restrict__ ent, const int* __restrict__ tail,
    const float* __restrict__ bih, const float* __restrict__ bhh) {
    int e = blockIdx.x * 8 + (threadIdx.x >> 5);
    if (e >= E_EDGES) return;
    int lane = threadIdx.x & 31;
    int hd = head[e], rl = rel[e], en = ent[e], tl = tail[e];
    const __half* ep = g_ent_proj + (size_t)en * G3H;
    const __half* nh = g_node_hh + (size_t)hd * G3H;
    const float4* rg = reinterpret_cast<const float4*>(g_rel_gru) + (size_t)rl * 96;
    const float4* bi = reinterpret_cast<const float4*>(bih);
    const float4* bh = reinterpret_cast<const float4*>(bhh);

    float4 ep_r = ld_half4(ep + lane * 4);
    float4 ep_z = ld_half4(ep + 128 + lane * 4);
    float4 ep_n = ld_half4(ep + 256 + lane * 4);
    float4 nh_r = ld_half4(nh + lane * 4);
    float4 nh_z = ld_half4(nh + 128 + lane * 4);
    float4 nh_n = ld_half4(nh + 256 + lane * 4);

    float4 gr = f4add3(ep_r, rg[lane],      bi[lane]);
    float4 hr = f4add (nh_r, bh[lane]);
    float4 gz = f4add3(ep_z, rg[lane + 32], bi[lane + 32]);
    float4 hz = f4add (nh_z, bh[lane + 32]);
    float4 gn = f4add3(ep_n, rg[lane + 64], bi[lane + 64]);
    float4 hn = f4add (nh_n, bh[lane + 64]);

    float4 r4 = sig4f(f4add(gr, hr));
    float4 z4 = sig4f(f4add(gz, hz));
    float4 n4;
    n4.x = tanh_fast(gn.x + r4.x * hn.x);
    n4.y = tanh_fast(gn.y + r4.y * hn.y);
    n4.z = tanh_fast(gn.z + r4.z * hn.z);
    n4.w = tanh_fast(gn.w + r4.w * hn.w);

    float4 hs = ld_half4(g_A16 + (size_t)hd * 128 + lane * 4);
    float alpha = g_ex[e] / (g_denom[tl] + 1e-6f);

    float mx = alpha * ((1.f - z4.x) * n4.x + z4.x * hs.x);
    float my = alpha * ((1.f - z4.y) * n4.y + z4.y * hs.y);
    float mz = alpha * ((1.f - z4.z) * n4.z + z4.z * hs.z);
    float mw = alpha * ((1.f - z4.w) * n4.w + z4.w * hs.w);

    float* dst = &g_agg[(size_t)tl * H_DIM + lane * 4];
    asm volatile("red.global.add.v4.f32 [%0], {%1,%2,%3,%4};"
                 :: "l"(dst), "f"(mx), "f"(my), "f"(mz), "f"(mw) : "memory");
}

// ---------------- launcher ----------------
extern "C" void kernel_launch(void* const* d_in, const int* in_sizes, int n_in,
                              void* d_out, int out_size) {
    const int*   head      = (const int*)d_in[0];
    const int*   rel       = (const int*)d_in[1];
    const int*   ent       = (const int*)d_in[2];
    const int*   tail      = (const int*)d_in[3];
    const int*   qidx      = (const int*)d_in[4];
    const float* node_emb  = (const float*)d_in[5];
    const float* ent_table = (const float*)d_in[6];
    const float* rel_table = (const float*)d_in[7];
    const float* Ws        = (const float*)d_in[8];
    const float* Wr        = (const float*)d_in[9];
    const float* Wqr       = (const float*)d_in[10];
    const float* bqr       = (const float*)d_in[11];
    const float* Wa        = (const float*)d_in[12];
    const float* ba        = (const float*)d_in[13];
    const float* W_ih      = (const float*)d_in[14];
    const float* W_hh      = (const float*)d_in[15];
    const float* bih       = (const float*)d_in[16];
    const float* bhh       = (const float*)d_in[17];
    const float* Wh        = (const float*)d_in[18];
    const float* lng       = (const float*)d_in[19];
    const float* lnb       = (const float*)d_in[20];
    float* out = (float*)d_out;

    float *p_agg;
    __half *p_ns16, *p_node_hh, *p_ent_proj, *p_A16, *p_E16, *p_Ws16, *p_Whh16, *p_Wih16, *p_Wh16, *p_agg16;
    cudaGetSymbolAddress((void**)&p_ns16,     g_ns16);
    cudaGetSymbolAddress((void**)&p_node_hh,  g_node_hh);
    cudaGetSymbolAddress((void**)&p_ent_proj, g_ent_proj);
    cudaGetSymbolAddress((void**)&p_agg,      g_agg);
    cudaGetSymbolAddress((void**)&p_agg16,    g_agg16);
    cudaGetSymbolAddress((void**)&p_A16,   g_A16);
    cudaGetSymbolAddress((void**)&p_E16,   g_E16);
    cudaGetSymbolAddress((void**)&p_Ws16,  g_Ws16);
    cudaGetSymbolAddress((void**)&p_Whh16, g_Whh16);
    cudaGetSymbolAddress((void**)&p_Wih16, g_Wih16);
    cudaGetSymbolAddress((void**)&p_Wh16,  g_Wh16);

    cudaFuncSetAttribute(k_hmma16_nt<1>, cudaFuncAttributeMaxDynamicSharedMemorySize, HM16_SMEM);
    cudaFuncSetAttribute(k_hmma16_nt<3>, cudaFuncAttributeMaxDynamicSharedMemorySize, HM16_SMEM);
    cudaFuncSetAttribute(k_out16, cudaFuncAttributeMaxDynamicSharedMemorySize, HM16_SMEM);

    k_init<<<(NNEW * H_DIM + 255) / 256, 256>>>();
    k_rel<<<NREL, G3H>>>(rel_table, Wr, Wqr, W_ih, bqr);
    // fp16 plane conversions
    k_cvt16<<<(NOLD * 32 + 255) / 256, 256>>>(node_emb, H_DIM, H_DIM, p_A16, NOLD);
    k_cvt16<<<(128 * 32 + 255) / 256, 256>>>(Ws, H_DIM, H_DIM, p_Ws16, 128);
    k_cvt16<<<(NENT * 32 + 255) / 256, 256>>>(ent_table, D_EMB, D_EMB, p_E16, NENT);
    k_cvt16<<<(G3H * 32 + 255) / 256, 256>>>(W_hh, H_DIM, H_DIM,     p_Whh16, G3H);
    k_cvt16<<<(G3H * 32 + 255) / 256, 256>>>(W_ih, D_EMB, 2 * D_EMB, p_Wih16, G3H);
    k_cvt16<<<(128 * 32 + 255) / 256, 256>>>(Wh, H_DIM, H_DIM, p_Wh16, 128);
    // precompute GEMMs (all fp16 single-MMA)
    {
        int grid = (NOLD + 127) / 128;
        k_hmma16_nt<1><<<grid, 256, HM16_SMEM>>>(p_A16, p_Ws16, p_ns16, NOLD);
        k_hmma16_nt<3><<<grid, 256, HM16_SMEM>>>(p_A16, p_Whh16, p_node_hh, NOLD);
        int gride = (NENT + 127) / 128;
        k_hmma16_nt<3><<<gride, 256, HM16_SMEM>>>(p_E16, p_Wih16, p_ent_proj, NENT);
    }
    // pass A: exp(logit) + denom (single edge pass)
    k_logit<<<E_EDGES / 8, 256>>>(head, rel, qidx, tail, Wa, ba);
    // pass C: gates + weighted scatter
    k_msg<<<E_EDGES / 8, 256>>>(head, rel, ent, tail, bih, bhh);
    // out: agg -> fp16 plane, HMMA GEMM + relu + LayerNorm
    k_cvt16<<<(NNEW * 32 + 255) / 256, 256>>>(p_agg, H_DIM, H_DIM, p_agg16, NNEW);
    k_out16<<<(NNEW + 127) / 128, 256, HM16_SMEM>>>(p_agg16, p_Wh16, lng, lnb, out, NNEW);
}